// round 9
// baseline (speedup 1.0000x reference)
#include <cuda_runtime.h>
#include <cuda_fp16.h>
#include <stdint.h>

#define HID   4096
#define SEQ   2048
#define BATCH 2
#define NH    32
#define HD    128
#define MROWS (BATCH*SEQ)
#define NQKV  (3*HID)

// fp16 scratch (device globals)
__device__ __half g_ah  [(size_t)MROWS*HID];
__device__ __half g_wqkvT[(size_t)NQKV*HID];
__device__ __half g_wdT [(size_t)HID*HID];
__device__ __half g_qh  [(size_t)BATCH*NH*SEQ*HD];   // pre-scaled
__device__ __half g_kh  [(size_t)BATCH*NH*SEQ*HD];
__device__ __half g_vT  [(size_t)BATCH*NH*HD*SEQ];   // [bh][d][s]
__device__ __half g_ctxh[(size_t)MROWS*HID];

// ============================ helpers ======================================
__device__ __forceinline__ uint32_t smem_u32(const void* p) {
    uint32_t a;
    asm("{ .reg .u64 t; cvta.to.shared.u64 t, %1; cvt.u32.u64 %0, t; }" : "=r"(a) : "l"(p));
    return a;
}
__device__ __forceinline__ void ldsm4(uint32_t* r, uint32_t addr) {
    asm volatile("ldmatrix.sync.aligned.m8n8.x4.shared.b16 {%0,%1,%2,%3}, [%4];"
                 : "=r"(r[0]), "=r"(r[1]), "=r"(r[2]), "=r"(r[3]) : "r"(addr));
}
__device__ __forceinline__ void mma16816(float* d, const uint32_t* a, const uint32_t* b) {
    asm volatile("mma.sync.aligned.m16n8k16.row.col.f32.f16.f16.f32 "
                 "{%0,%1,%2,%3}, {%4,%5,%6,%7}, {%8,%9}, {%0,%1,%2,%3};"
                 : "+f"(d[0]), "+f"(d[1]), "+f"(d[2]), "+f"(d[3])
                 : "r"(a[0]), "r"(a[1]), "r"(a[2]), "r"(a[3]), "r"(b[0]), "r"(b[1]));
}
__device__ __forceinline__ uint32_t pack_h(float a, float b) {
    __half2 hh = __floats2half2_rn(a, b);
    return *(uint32_t*)&hh;
}
__device__ __forceinline__ void cpa16(uint32_t dst, const void* src) {
    asm volatile("cp.async.cg.shared.global [%0], [%1], 16;" :: "r"(dst), "l"(src));
}
#define CP_COMMIT() asm volatile("cp.async.commit_group;" ::: "memory")
#define CP_WAIT(n)  asm volatile("cp.async.wait_group %0;" :: "n"(n) : "memory")

// ===================== conversion prologue kernels =========================
__global__ void conv_fp16_kernel(const float* __restrict__ src,
                                 __half* __restrict__ dst, int n4)
{
    const int i = blockIdx.x * blockDim.x + threadIdx.x;
    if (i < n4) {
        float4 v = ((const float4*)src)[i];
        uint2 o;
        o.x = pack_h(v.x, v.y);
        o.y = pack_h(v.z, v.w);
        ((uint2*)dst)[i] = o;
    }
}
__global__ void transpose_fp16_kernel(const float* __restrict__ src,
                                      __half* __restrict__ dst, int R, int C)
{
    __shared__ float t[32][33];
    const int x = blockIdx.x * 32 + threadIdx.x;
    const int y0 = blockIdx.y * 32;
    #pragma unroll
    for (int j = 0; j < 4; j++)
        t[threadIdx.y + j * 8][threadIdx.x] = src[(size_t)(y0 + threadIdx.y + j * 8) * C + x];
    __syncthreads();
    const int xo = y0 + threadIdx.x;
    const int yo0 = blockIdx.x * 32;
    #pragma unroll
    for (int j = 0; j < 4; j++)
        dst[(size_t)(yo0 + threadIdx.y + j * 8) * R + xo] =
            __float2half(t[threadIdx.x][threadIdx.y + j * 8]);
}

// ====================== fp16 GEMM: 4 warps, 64x64 warp tile ================
#define KCH    64
#define ROWB   144                 /* 128B data + 16B pad; phase r*9%8 conflict-free */
#define PLANE  (128*ROWB)          /* 18432 */
#define STAGE  (2*PLANE)           /* 36864 */
#define GEMM_SMEM (2*STAGE)        /* 73728 */

template <bool IS_QKV>
__global__ void __launch_bounds__(128, 2)
gemm_mma_kernel(const __half* __restrict__ Ah, const __half* __restrict__ Wt,
                const float* __restrict__ bias, const float* __restrict__ resid,
                float* __restrict__ out)
{
    constexpr int NC = HID / KCH;   // 64
    extern __shared__ __align__(16) char stg[];
    const uint32_t stg_u = smem_u32(stg);

    const int tid = threadIdx.x;
    const int wid = tid >> 5, lane = tid & 31;
    const int wm  = wid >> 1, wn = wid & 1;     // 2x2 warp grid, 64x64 tiles
    const int m0  = blockIdx.y * 128, n0 = blockIdx.x * 128;

    // loader: one 128B row-chunk per thread per plane
    const __half* aP = Ah + (size_t)(m0 + tid) * HID;
    const __half* bP = Wt + (size_t)(n0 + tid) * HID;
    const uint32_t sA = stg_u + tid * ROWB;
    const uint32_t sB = stg_u + PLANE + tid * ROWB;

    float acc[4][8][4];
    #pragma unroll
    for (int mi = 0; mi < 4; mi++)
        #pragma unroll
        for (int nj = 0; nj < 8; nj++)
            #pragma unroll
            for (int r = 0; r < 4; r++) acc[mi][nj][r] = 0.f;

    const uint32_t a_base = stg_u + (uint32_t)(wm * 64 + (lane & 15)) * ROWB + ((lane >> 4) << 4);
    const uint32_t b_base = stg_u + PLANE
                          + (uint32_t)(wn * 64 + (lane & 7) + ((lane >> 4) << 3)) * ROWB
                          + (((lane >> 3) & 1) << 4);

    // issue chunk c into buffer buf
    {
        #pragma unroll
        for (int i = 0; i < 8; i++) {
            cpa16(sA + i * 16, aP + i * 8);
            cpa16(sB + i * 16, bP + i * 8);
        }
        CP_COMMIT();
    }

    for (int c = 0; c < NC; c++) {
        const int cur = c & 1;
        const bool more = (c + 1 < NC);
        if (more) {
            const int k0 = (c + 1) * KCH;
            const uint32_t off = (cur ^ 1) * STAGE;
            #pragma unroll
            for (int i = 0; i < 8; i++) {
                cpa16(sA + off + i * 16, aP + k0 + i * 8);
                cpa16(sB + off + i * 16, bP + k0 + i * 8);
            }
            CP_COMMIT();
            CP_WAIT(1);
        } else {
            CP_WAIT(0);
        }
        __syncthreads();

        const uint32_t ab = a_base + cur * STAGE;
        const uint32_t bb = b_base + cur * STAGE;
        #pragma unroll
        for (int kk = 0; kk < 4; kk++) {
            uint32_t aH[4][4], bF[4][4];
            #pragma unroll
            for (int mi = 0; mi < 4; mi++) ldsm4(aH[mi], ab + kk * 32 + mi * 16 * ROWB);
            #pragma unroll
            for (int j2 = 0; j2 < 4; j2++) ldsm4(bF[j2], bb + kk * 32 + j2 * 16 * ROWB);
            #pragma unroll
            for (int mi = 0; mi < 4; mi++)
                #pragma unroll
                for (int j2 = 0; j2 < 4; j2++) {
                    mma16816(acc[mi][2*j2],   aH[mi], &bF[j2][0]);
                    mma16816(acc[mi][2*j2+1], aH[mi], &bF[j2][2]);
                }
        }
        __syncthreads();
    }

    // ---------------------------- epilogue ---------------------------------
    const float inv_norm = 0.088388347648318447f;
    float b2x[8], b2y[8];
    #pragma unroll
    for (int nj = 0; nj < 8; nj++) {
        const int col = n0 + wn * 64 + nj * 8 + (lane & 3) * 2;
        b2x[nj] = __ldg(&bias[col]);
        b2y[nj] = __ldg(&bias[col + 1]);
    }
    if (IS_QKV) {
        const int h = blockIdx.x / 3, comp = blockIdx.x % 3;
        #pragma unroll
        for (int mi = 0; mi < 4; mi++) {
            #pragma unroll
            for (int rr = 0; rr < 2; rr++) {
                const int row = m0 + wm * 64 + mi * 16 + (lane >> 2) + rr * 8;
                const int bbat = row >> 11, ss = row & 2047;
                #pragma unroll
                for (int nj = 0; nj < 8; nj++) {
                    const int d = wn * 64 + nj * 8 + (lane & 3) * 2;
                    float vx = acc[mi][nj][rr*2]   + b2x[nj];
                    float vy = acc[mi][nj][rr*2+1] + b2y[nj];
                    if (comp == 0) {
                        __half* dst = g_qh + ((size_t)(bbat * NH + h) * SEQ + ss) * HD + d;
                        *(uint32_t*)dst = pack_h(vx * inv_norm, vy * inv_norm);
                    } else if (comp == 1) {
                        __half* dst = g_kh + ((size_t)(bbat * NH + h) * SEQ + ss) * HD + d;
                        *(uint32_t*)dst = pack_h(vx, vy);
                    } else {
                        __half* dst = g_vT + ((size_t)(bbat * NH + h) * HD + d) * SEQ + ss;
                        dst[0]   = __float2half(vx);
                        dst[SEQ] = __float2half(vy);
                    }
                }
            }
        }
    } else {
        #pragma unroll
        for (int mi = 0; mi < 4; mi++) {
            #pragma unroll
            for (int rr = 0; rr < 2; rr++) {
                const int row = m0 + wm * 64 + mi * 16 + (lane >> 2) + rr * 8;
                const size_t o = (size_t)row * HID + n0 + wn * 64 + (lane & 3) * 2;
                #pragma unroll
                for (int nj = 0; nj < 8; nj++) {
                    float2 rv = *(const float2*)(resid + o + nj * 8);
                    *(float2*)(out + o + nj * 8) =
                        make_float2(acc[mi][nj][rr*2] + b2x[nj] + rv.x,
                                    acc[mi][nj][rr*2+1] + b2y[nj] + rv.y);
                }
            }
        }
    }
}

// ============ flash attention: cp.async double-buffered K/V ================
// planes (stride 272B, 128 rows): Q | P | K0 | V0 | K1 | V1
#define STR  272
#define PLN  (128*STR)
#define ATT_SMEM (6*PLN)           /* 208896 */

__global__ void __launch_bounds__(256, 1) attn_mma_kernel(const float* __restrict__ alibi)
{
    extern __shared__ __align__(16) char sm[];
    char* Qh = sm;
    char* Pp = sm + PLN;
    __shared__ float red_mx[2][128];
    __shared__ float red_sm[2][128];

    const int tid = threadIdx.x;
    const int wid = tid >> 5, lane = tid & 31;
    const int wm = wid >> 1, wn = wid & 1;
    const int qt = gridDim.x - 1 - blockIdx.x;
    const int bh = blockIdx.y;
    const int q0 = qt * 128;

    // Q plain copy (pre-scaled fp16)
    {
        const int r = tid >> 1, c = (tid & 1) * 64;
        const __half* p = g_qh + ((size_t)bh * SEQ + q0) * HD + (size_t)r * HD + c;
        char* d = Qh + r * STR + c * 2;
        #pragma unroll
        for (int i = 0; i < 8; i++)
            *(uint4*)(d + i * 16) = *(const uint4*)(p + i * 8);
    }

    const __half* kgl = g_kh + (size_t)bh * SEQ * HD;
    const __half* vgl = g_vT + (size_t)bh * HD * SEQ;
    const int lr = tid >> 1, lc = (tid & 1) * 64;
    const uint32_t kdst0 = smem_u32(sm) + 2 * PLN + lr * STR + lc * 2;

    // issue K/V tile kt into buffer buf
    auto issueKV = [&](int kt, int buf) {
        const __half* kp = kgl + (size_t)(kt * 128 + lr) * HD + lc;
        const __half* vp = vgl + (size_t)lr * SEQ + kt * 128 + lc;
        const uint32_t kd = kdst0 + buf * 2 * PLN;
        #pragma unroll
        for (int i = 0; i < 8; i++) {
            cpa16(kd + i * 16, kp + i * 8);
            cpa16(kd + PLN + i * 16, vp + i * 8);
        }
        CP_COMMIT();
    };

    const uint32_t a_off = (uint32_t)(wm * 32 + (lane & 15)) * STR + ((lane >> 4) << 4);
    const uint32_t b_off = (uint32_t)(wn * 64 + (lane & 7) + ((lane >> 4) << 3)) * STR
                         + (((lane >> 3) & 1) << 4);
    const uint32_t qh_b = smem_u32(Qh) + a_off;
    const uint32_t ph_b = smem_u32(Pp) + a_off;

    float o[2][8][4];
    float m_[2][2], l_[2][2], corr[2][2];
    #pragma unroll
    for (int mi = 0; mi < 2; mi++)
        #pragma unroll
        for (int rr = 0; rr < 2; rr++) { m_[mi][rr] = -1e30f; l_[mi][rr] = 0.f; }
    #pragma unroll
    for (int mi = 0; mi < 2; mi++)
        #pragma unroll
        for (int nj = 0; nj < 8; nj++)
            #pragma unroll
            for (int r = 0; r < 4; r++) o[mi][nj][r] = 0.f;

    const float* albase = alibi + (size_t)bh * SEQ;
    const int rbase = wm * 32 + (lane >> 2);

    issueKV(0, 0);

    for (int kt = 0; kt <= qt; kt++) {
        const int cur = kt & 1;
        const bool more = (kt < qt);
        if (more) { issueKV(kt + 1, cur ^ 1); CP_WAIT(1); }
        else      { CP_WAIT(0); }
        __syncthreads();

        const uint32_t kh_b = smem_u32(sm) + (2 + 2 * cur) * PLN + b_off;
        const uint32_t vh_b = kh_b + PLN;
        const int k0 = kt * 128;

        // S = Q K^T
        float s[2][8][4];
        #pragma unroll
        for (int mi = 0; mi < 2; mi++)
            #pragma unroll
            for (int nj = 0; nj < 8; nj++)
                #pragma unroll
                for (int r = 0; r < 4; r++) s[mi][nj][r] = 0.f;
        #pragma unroll
        for (int kk = 0; kk < 8; kk++) {
            uint32_t aH[2][4], bF[4][4];
            ldsm4(aH[0], qh_b + kk * 32);
            ldsm4(aH[1], qh_b + kk * 32 + 16 * STR);
            #pragma unroll
            for (int j2 = 0; j2 < 4; j2++) ldsm4(bF[j2], kh_b + kk * 32 + j2 * 16 * STR);
            #pragma unroll
            for (int mi = 0; mi < 2; mi++)
                #pragma unroll
                for (int j2 = 0; j2 < 4; j2++) {
                    mma16816(s[mi][2*j2],   aH[mi], &bF[j2][0]);
                    mma16816(s[mi][2*j2+1], aH[mi], &bF[j2][2]);
                }
        }

        // alibi + causal mask + partial row max
        float al[8][2];
        #pragma unroll
        for (int nj = 0; nj < 8; nj++) {
            const int col = k0 + wn * 64 + nj * 8 + (lane & 3) * 2;
            al[nj][0] = __ldg(albase + col);
            al[nj][1] = __ldg(albase + col + 1);
        }
        const bool diag = (kt == qt);
        #pragma unroll
        for (int mi = 0; mi < 2; mi++) {
            #pragma unroll
            for (int rr = 0; rr < 2; rr++) {
                const int rloc = rbase + mi * 16 + rr * 8;
                const int rowg = q0 + rloc;
                float mx = -1e30f;
                #pragma unroll
                for (int nj = 0; nj < 8; nj++) {
                    #pragma unroll
                    for (int e = 0; e < 2; e++) {
                        float v = s[mi][nj][rr*2+e] + al[nj][e];
                        if (diag && (k0 + wn*64 + nj*8 + (lane&3)*2 + e) > rowg) v = -1e30f;
                        s[mi][nj][rr*2+e] = v;
                        mx = fmaxf(mx, v);
                    }
                }
                mx = fmaxf(mx, __shfl_xor_sync(0xffffffffu, mx, 1));
                mx = fmaxf(mx, __shfl_xor_sync(0xffffffffu, mx, 2));
                if ((lane & 3) == 0) red_mx[wn][rloc] = mx;
            }
        }
        __syncthreads();

        // softmax
        #pragma unroll
        for (int mi = 0; mi < 2; mi++) {
            #pragma unroll
            for (int rr = 0; rr < 2; rr++) {
                const int rloc = rbase + mi * 16 + rr * 8;
                const float mx = fmaxf(red_mx[0][rloc], red_mx[1][rloc]);
                const float mnew = fmaxf(m_[mi][rr], mx);
                const float cr = __expf(m_[mi][rr] - mnew);
                corr[mi][rr] = cr;
                m_[mi][rr] = mnew;
                float ls = 0.f;
                #pragma unroll
                for (int nj = 0; nj < 8; nj++) {
                    #pragma unroll
                    for (int e = 0; e < 2; e++) {
                        float p = __expf(s[mi][nj][rr*2+e] - mnew);
                        s[mi][nj][rr*2+e] = p;
                        ls += p;
                    }
                }
                ls += __shfl_xor_sync(0xffffffffu, ls, 1);
                ls += __shfl_xor_sync(0xffffffffu, ls, 2);
                if ((lane & 3) == 0) red_sm[wn][rloc] = ls;
                #pragma unroll
                for (int nj = 0; nj < 8; nj++) {
                    o[mi][nj][rr*2]   *= cr;
                    o[mi][nj][rr*2+1] *= cr;
                }
            }
        }
        __syncthreads();
        #pragma unroll
        for (int mi = 0; mi < 2; mi++)
            #pragma unroll
            for (int rr = 0; rr < 2; rr++) {
                const int rloc = rbase + mi * 16 + rr * 8;
                l_[mi][rr] = l_[mi][rr] * corr[mi][rr] + red_sm[0][rloc] + red_sm[1][rloc];
            }

        // write P (fp16) into P plane
        #pragma unroll
        for (int mi = 0; mi < 2; mi++) {
            #pragma unroll
            for (int rr = 0; rr < 2; rr++) {
                const uint32_t roff = (uint32_t)(rbase + mi * 16 + rr * 8) * STR
                                    + (wn * 64 + (lane & 3) * 2) * 2;
                #pragma unroll
                for (int nj = 0; nj < 8; nj++)
                    *(uint32_t*)(Pp + roff + nj * 16) =
                        pack_h(s[mi][nj][rr*2], s[mi][nj][rr*2+1]);
            }
        }
        __syncthreads();

        // O += P V
        #pragma unroll
        for (int kk = 0; kk < 8; kk++) {
            uint32_t aH[2][4], bF[4][4];
            ldsm4(aH[0], ph_b + kk * 32);
            ldsm4(aH[1], ph_b + kk * 32 + 16 * STR);
            #pragma unroll
            for (int j2 = 0; j2 < 4; j2++) ldsm4(bF[j2], vh_b + kk * 32 + j2 * 16 * STR);
            #pragma unroll
            for (int mi = 0; mi < 2; mi++)
                #pragma unroll
                for (int j2 = 0; j2 < 4; j2++) {
                    mma16816(o[mi][2*j2],   aH[mi], &bF[j2][0]);
                    mma16816(o[mi][2*j2+1], aH[mi], &bF[j2][2]);
                }
        }
        __syncthreads();
    }

    // epilogue -> fp16 ctx
    const int b = bh >> 5, h = bh & 31;
    #pragma unroll
    for (int mi = 0; mi < 2; mi++) {
        #pragma unroll
        for (int rr = 0; rr < 2; rr++) {
            const float invl = 1.f / l_[mi][rr];
            const int srow = q0 + rbase + mi * 16 + rr * 8;
            __half* op = g_ctxh + ((size_t)(b * SEQ + srow)) * HID + h * HD
                       + wn * 64 + (lane & 3) * 2;
            #pragma unroll
            for (int nj = 0; nj < 8; nj++)
                *(uint32_t*)(op + nj * 8) = pack_h(o[mi][nj][rr*2] * invl,
                                                   o[mi][nj][rr*2+1] * invl);
        }
    }
}

// =============================== launch ====================================
extern "C" void kernel_launch(void* const* d_in, const int* in_sizes, int n_in,
                              void* d_out, int out_size)
{
    const float* hs    = (const float*)d_in[0];
    const float* resid = (const float*)d_in[1];
    const float* alibi = (const float*)d_in[2];
    const float* Wqkv  = (const float*)d_in[4];
    const float* bqkv  = (const float*)d_in[5];
    const float* Wd    = (const float*)d_in[6];
    const float* bd    = (const float*)d_in[7];
    float* out = (float*)d_out;

    cudaFuncSetAttribute(gemm_mma_kernel<true>,
                         cudaFuncAttributeMaxDynamicSharedMemorySize, GEMM_SMEM);
    cudaFuncSetAttribute(gemm_mma_kernel<false>,
                         cudaFuncAttributeMaxDynamicSharedMemorySize, GEMM_SMEM);
    cudaFuncSetAttribute(attn_mma_kernel,
                         cudaFuncAttributeMaxDynamicSharedMemorySize, ATT_SMEM);

    __half* d_ah;    cudaGetSymbolAddress((void**)&d_ah,    g_ah);
    __half* d_wqkvT; cudaGetSymbolAddress((void**)&d_wqkvT, g_wqkvT);
    __half* d_wdT;   cudaGetSymbolAddress((void**)&d_wdT,   g_wdT);
    __half* d_ctxh;  cudaGetSymbolAddress((void**)&d_ctxh,  g_ctxh);

    conv_fp16_kernel<<<(MROWS * HID / 4 + 255) / 256, 256>>>(hs, d_ah, MROWS * HID / 4);
    transpose_fp16_kernel<<<dim3(NQKV / 32, HID / 32), dim3(32, 8)>>>(Wqkv, d_wqkvT, HID, NQKV);
    transpose_fp16_kernel<<<dim3(HID / 32, HID / 32), dim3(32, 8)>>>(Wd, d_wdT, HID, HID);

    gemm_mma_kernel<true><<<dim3(NQKV/128, MROWS/128), 128, GEMM_SMEM>>>(d_ah, d_wqkvT, bqkv, nullptr, nullptr);
    attn_mma_kernel<<<dim3(SEQ/128, BATCH*NH), 256, ATT_SMEM>>>(alibi);
    gemm_mma_kernel<false><<<dim3(HID/128, MROWS/128), 128, GEMM_SMEM>>>(d_ctxh, d_wdT, bd, resid, out);
}

// round 10
// speedup vs baseline: 1.3821x; 1.3821x over previous
#include <cuda_runtime.h>
#include <cuda_fp16.h>
#include <stdint.h>

#define HID   4096
#define SEQ   2048
#define BATCH 2
#define NH    32
#define HD    128
#define MROWS (BATCH*SEQ)
#define NQKV  (3*HID)

__device__ __half g_ah  [(size_t)MROWS*HID];
__device__ __half g_wqkvT[(size_t)NQKV*HID];
__device__ __half g_wdT [(size_t)HID*HID];
__device__ __half g_qh  [(size_t)BATCH*NH*SEQ*HD];   // pre-scaled
__device__ __half g_kh  [(size_t)BATCH*NH*SEQ*HD];
__device__ __half g_vT  [(size_t)BATCH*NH*HD*SEQ];   // [bh][d][s]
__device__ __half g_ctxh[(size_t)MROWS*HID];

// ============================ helpers ======================================
__device__ __forceinline__ uint32_t smem_u32(const void* p) {
    uint32_t a;
    asm("{ .reg .u64 t; cvta.to.shared.u64 t, %1; cvt.u32.u64 %0, t; }" : "=r"(a) : "l"(p));
    return a;
}
__device__ __forceinline__ void ldsm4(uint32_t* r, uint32_t addr) {
    asm volatile("ldmatrix.sync.aligned.m8n8.x4.shared.b16 {%0,%1,%2,%3}, [%4];"
                 : "=r"(r[0]), "=r"(r[1]), "=r"(r[2]), "=r"(r[3]) : "r"(addr));
}
__device__ __forceinline__ void mma16816(float* d, const uint32_t* a, const uint32_t* b) {
    asm volatile("mma.sync.aligned.m16n8k16.row.col.f32.f16.f16.f32 "
                 "{%0,%1,%2,%3}, {%4,%5,%6,%7}, {%8,%9}, {%0,%1,%2,%3};"
                 : "+f"(d[0]), "+f"(d[1]), "+f"(d[2]), "+f"(d[3])
                 : "r"(a[0]), "r"(a[1]), "r"(a[2]), "r"(a[3]), "r"(b[0]), "r"(b[1]));
}
__device__ __forceinline__ uint32_t pack_h(float a, float b) {
    __half2 hh = __floats2half2_rn(a, b);
    return *(uint32_t*)&hh;
}
__device__ __forceinline__ void cpa16(uint32_t dst, const void* src) {
    asm volatile("cp.async.cg.shared.global [%0], [%1], 16;" :: "r"(dst), "l"(src));
}
#define CP_COMMIT() asm volatile("cp.async.commit_group;" ::: "memory")
#define CP_WAIT(n)  asm volatile("cp.async.wait_group %0;" :: "n"(n) : "memory")

// ===================== conversion prologue kernels =========================
__global__ void conv_fp16_kernel(const float* __restrict__ src,
                                 __half* __restrict__ dst, int n4)
{
    const int i = blockIdx.x * blockDim.x + threadIdx.x;
    if (i < n4) {
        float4 v = ((const float4*)src)[i];
        uint2 o;
        o.x = pack_h(v.x, v.y);
        o.y = pack_h(v.z, v.w);
        ((uint2*)dst)[i] = o;
    }
}
__global__ void transpose_fp16_kernel(const float* __restrict__ src,
                                      __half* __restrict__ dst, int R, int C)
{
    __shared__ float t[32][33];
    const int x = blockIdx.x * 32 + threadIdx.x;
    const int y0 = blockIdx.y * 32;
    #pragma unroll
    for (int j = 0; j < 4; j++)
        t[threadIdx.y + j * 8][threadIdx.x] = src[(size_t)(y0 + threadIdx.y + j * 8) * C + x];
    __syncthreads();
    const int xo = y0 + threadIdx.x;
    const int yo0 = blockIdx.x * 32;
    #pragma unroll
    for (int j = 0; j < 4; j++)
        dst[(size_t)(yo0 + threadIdx.y + j * 8) * R + xo] =
            __float2half(t[threadIdx.x][threadIdx.y + j * 8]);
}

// ============ fp16 GEMM: CTA 256x128, 16 warps (4x4), warp tile 64x32 ======
#define KCH    32
#define ROWB   80
#define APLANE (256*ROWB)          /* 20480 */
#define BPLANE (128*ROWB)          /* 10240 */
#define STAGE  (APLANE+BPLANE)     /* 30720 */
#define GEMM_SMEM (2*STAGE)        /* 61440 */

template <bool IS_QKV>
__global__ void __launch_bounds__(512, 1)
gemm_mma_kernel(const __half* __restrict__ Ah, const __half* __restrict__ Wt,
                const float* __restrict__ bias, const float* __restrict__ resid,
                float* __restrict__ out)
{
    constexpr int NC = HID / KCH;   // 128
    extern __shared__ __align__(16) char stg[];
    const uint32_t stg_u = smem_u32(stg);

    const int tid = threadIdx.x;
    const int wid = tid >> 5, lane = tid & 31;
    const int wm  = wid >> 2, wn = wid & 3;      // 4x4 grid, warp tile 64x32
    const int m0  = blockIdx.y * 256, n0 = blockIdx.x * 128;

    // loader tasks (16B each): A 256 rows x 4 chunks = 1024 (2/thread), B 512 (1/thread)
    const int ar0 = (tid) >> 2,        ac0 = (tid & 3);
    const int ar1 = (tid + 512) >> 2,  ac1 = ((tid + 512) & 3);
    const int br  = tid >> 2,          bc  = (tid & 3);
    const __half* aS0 = Ah + (size_t)(m0 + ar0) * HID + ac0 * 8;
    const __half* aS1 = Ah + (size_t)(m0 + ar1) * HID + ac1 * 8;
    const __half* bS  = Wt + (size_t)(n0 + br) * HID + bc * 8;
    const uint32_t aD0 = stg_u + ar0 * ROWB + ac0 * 16;
    const uint32_t aD1 = stg_u + ar1 * ROWB + ac1 * 16;
    const uint32_t bD  = stg_u + APLANE + br * ROWB + bc * 16;

    float acc[4][4][4];
    #pragma unroll
    for (int mi = 0; mi < 4; mi++)
        #pragma unroll
        for (int nj = 0; nj < 4; nj++)
            #pragma unroll
            for (int r = 0; r < 4; r++) acc[mi][nj][r] = 0.f;

    const uint32_t a_base = stg_u + (uint32_t)(wm * 64 + (lane & 15)) * ROWB + ((lane >> 4) << 4);
    const uint32_t b_base = stg_u + APLANE
                          + (uint32_t)(wn * 32 + (lane & 7) + ((lane >> 4) << 3)) * ROWB
                          + (((lane >> 3) & 1) << 4);

    // prologue: chunk 0 -> buffer 0
    cpa16(aD0, aS0); cpa16(aD1, aS1); cpa16(bD, bS);
    CP_COMMIT();

    for (int c = 0; c < NC; c++) {
        const int cur = c & 1;
        const bool more = (c + 1 < NC);
        if (more) {
            const int k0 = (c + 1) * KCH;
            const uint32_t off = (cur ^ 1) * STAGE;
            cpa16(aD0 + off, aS0 + k0);
            cpa16(aD1 + off, aS1 + k0);
            cpa16(bD + off, bS + k0);
            CP_COMMIT();
            CP_WAIT(1);
        } else {
            CP_WAIT(0);
        }
        __syncthreads();

        const uint32_t ab = a_base + cur * STAGE;
        const uint32_t bb = b_base + cur * STAGE;
        #pragma unroll
        for (int kk = 0; kk < 2; kk++) {
            uint32_t aH[4][4], bF[2][4];
            #pragma unroll
            for (int mi = 0; mi < 4; mi++) ldsm4(aH[mi], ab + kk * 32 + mi * 16 * ROWB);
            #pragma unroll
            for (int j2 = 0; j2 < 2; j2++) ldsm4(bF[j2], bb + kk * 32 + j2 * 16 * ROWB);
            #pragma unroll
            for (int mi = 0; mi < 4; mi++)
                #pragma unroll
                for (int j2 = 0; j2 < 2; j2++) {
                    mma16816(acc[mi][2*j2],   aH[mi], &bF[j2][0]);
                    mma16816(acc[mi][2*j2+1], aH[mi], &bF[j2][2]);
                }
        }
        __syncthreads();
    }

    // ---------------------------- epilogue ---------------------------------
    const float inv_norm = 0.088388347648318447f;
    float b2x[4], b2y[4];
    #pragma unroll
    for (int nj = 0; nj < 4; nj++) {
        const int col = n0 + wn * 32 + nj * 8 + (lane & 3) * 2;
        b2x[nj] = __ldg(&bias[col]);
        b2y[nj] = __ldg(&bias[col + 1]);
    }
    if (IS_QKV) {
        const int h = blockIdx.x / 3, comp = blockIdx.x % 3;
        #pragma unroll
        for (int mi = 0; mi < 4; mi++) {
            #pragma unroll
            for (int rr = 0; rr < 2; rr++) {
                const int row = m0 + wm * 64 + mi * 16 + (lane >> 2) + rr * 8;
                const int bbat = row >> 11, ss = row & 2047;
                #pragma unroll
                for (int nj = 0; nj < 4; nj++) {
                    const int d = wn * 32 + nj * 8 + (lane & 3) * 2;
                    float vx = acc[mi][nj][rr*2]   + b2x[nj];
                    float vy = acc[mi][nj][rr*2+1] + b2y[nj];
                    if (comp == 0) {
                        __half* dst = g_qh + ((size_t)(bbat * NH + h) * SEQ + ss) * HD + d;
                        *(uint32_t*)dst = pack_h(vx * inv_norm, vy * inv_norm);
                    } else if (comp == 1) {
                        __half* dst = g_kh + ((size_t)(bbat * NH + h) * SEQ + ss) * HD + d;
                        *(uint32_t*)dst = pack_h(vx, vy);
                    } else {
                        __half* dst = g_vT + ((size_t)(bbat * NH + h) * HD + d) * SEQ + ss;
                        dst[0]   = __float2half(vx);
                        dst[SEQ] = __float2half(vy);
                    }
                }
            }
        }
    } else {
        #pragma unroll
        for (int mi = 0; mi < 4; mi++) {
            #pragma unroll
            for (int rr = 0; rr < 2; rr++) {
                const int row = m0 + wm * 64 + mi * 16 + (lane >> 2) + rr * 8;
                const size_t o = (size_t)row * HID + n0 + wn * 32 + (lane & 3) * 2;
                #pragma unroll
                for (int nj = 0; nj < 4; nj++) {
                    float2 rv = *(const float2*)(resid + o + nj * 8);
                    *(float2*)(out + o + nj * 8) =
                        make_float2(acc[mi][nj][rr*2] + b2x[nj] + rv.x,
                                    acc[mi][nj][rr*2+1] + b2y[nj] + rv.y);
                }
            }
        }
    }
}

// ============ flash attention: cp.async double-buffered K/V ================
// planes (stride 272B, 128 rows): Q | P | K0 | V0 | K1 | V1
#define STR  272
#define PLN  (128*STR)
#define ATT_SMEM (6*PLN)

__global__ void __launch_bounds__(256, 1) attn_mma_kernel(const float* __restrict__ alibi)
{
    extern __shared__ __align__(16) char sm[];
    char* Qh = sm;
    char* Pp = sm + PLN;
    __shared__ float red_mx[2][128];
    __shared__ float red_sm[2][128];

    const int tid = threadIdx.x;
    const int wid = tid >> 5, lane = tid & 31;
    const int wm = wid >> 1, wn = wid & 1;
    const int qt = gridDim.x - 1 - blockIdx.x;
    const int bh = blockIdx.y;
    const int q0 = qt * 128;

    {
        const int r = tid >> 1, c = (tid & 1) * 64;
        const __half* p = g_qh + ((size_t)bh * SEQ + q0) * HD + (size_t)r * HD + c;
        char* d = Qh + r * STR + c * 2;
        #pragma unroll
        for (int i = 0; i < 8; i++)
            *(uint4*)(d + i * 16) = *(const uint4*)(p + i * 8);
    }

    const __half* kgl = g_kh + (size_t)bh * SEQ * HD;
    const __half* vgl = g_vT + (size_t)bh * HD * SEQ;
    const int lr = tid >> 1, lc = (tid & 1) * 64;
    const uint32_t kdst0 = smem_u32(sm) + 2 * PLN + lr * STR + lc * 2;

    auto issueKV = [&](int kt, int buf) {
        const __half* kp = kgl + (size_t)(kt * 128 + lr) * HD + lc;
        const __half* vp = vgl + (size_t)lr * SEQ + kt * 128 + lc;
        const uint32_t kd = kdst0 + buf * 2 * PLN;
        #pragma unroll
        for (int i = 0; i < 8; i++) {
            cpa16(kd + i * 16, kp + i * 8);
            cpa16(kd + PLN + i * 16, vp + i * 8);
        }
        CP_COMMIT();
    };

    const uint32_t a_off = (uint32_t)(wm * 32 + (lane & 15)) * STR + ((lane >> 4) << 4);
    const uint32_t b_off = (uint32_t)(wn * 64 + (lane & 7) + ((lane >> 4) << 3)) * STR
                         + (((lane >> 3) & 1) << 4);
    const uint32_t qh_b = smem_u32(Qh) + a_off;
    const uint32_t ph_b = smem_u32(Pp) + a_off;

    float o[2][8][4];
    float m_[2][2], l_[2][2], corr[2][2];
    #pragma unroll
    for (int mi = 0; mi < 2; mi++)
        #pragma unroll
        for (int rr = 0; rr < 2; rr++) { m_[mi][rr] = -1e30f; l_[mi][rr] = 0.f; }
    #pragma unroll
    for (int mi = 0; mi < 2; mi++)
        #pragma unroll
        for (int nj = 0; nj < 8; nj++)
            #pragma unroll
            for (int r = 0; r < 4; r++) o[mi][nj][r] = 0.f;

    const float* albase = alibi + (size_t)bh * SEQ;
    const int rbase = wm * 32 + (lane >> 2);

    issueKV(0, 0);

    for (int kt = 0; kt <= qt; kt++) {
        const int cur = kt & 1;
        const bool more = (kt < qt);
        if (more) { issueKV(kt + 1, cur ^ 1); CP_WAIT(1); }
        else      { CP_WAIT(0); }
        __syncthreads();

        const uint32_t kh_b = smem_u32(sm) + (2 + 2 * cur) * PLN + b_off;
        const uint32_t vh_b = kh_b + PLN;
        const int k0 = kt * 128;

        float s[2][8][4];
        #pragma unroll
        for (int mi = 0; mi < 2; mi++)
            #pragma unroll
            for (int nj = 0; nj < 8; nj++)
                #pragma unroll
                for (int r = 0; r < 4; r++) s[mi][nj][r] = 0.f;
        #pragma unroll
        for (int kk = 0; kk < 8; kk++) {
            uint32_t aH[2][4], bF[4][4];
            ldsm4(aH[0], qh_b + kk * 32);
            ldsm4(aH[1], qh_b + kk * 32 + 16 * STR);
            #pragma unroll
            for (int j2 = 0; j2 < 4; j2++) ldsm4(bF[j2], kh_b + kk * 32 + j2 * 16 * STR);
            #pragma unroll
            for (int mi = 0; mi < 2; mi++)
                #pragma unroll
                for (int j2 = 0; j2 < 4; j2++) {
                    mma16816(s[mi][2*j2],   aH[mi], &bF[j2][0]);
                    mma16816(s[mi][2*j2+1], aH[mi], &bF[j2][2]);
                }
        }

        float al[8][2];
        #pragma unroll
        for (int nj = 0; nj < 8; nj++) {
            const int col = k0 + wn * 64 + nj * 8 + (lane & 3) * 2;
            al[nj][0] = __ldg(albase + col);
            al[nj][1] = __ldg(albase + col + 1);
        }
        const bool diag = (kt == qt);
        #pragma unroll
        for (int mi = 0; mi < 2; mi++) {
            #pragma unroll
            for (int rr = 0; rr < 2; rr++) {
                const int rloc = rbase + mi * 16 + rr * 8;
                const int rowg = q0 + rloc;
                float mx = -1e30f;
                #pragma unroll
                for (int nj = 0; nj < 8; nj++) {
                    #pragma unroll
                    for (int e = 0; e < 2; e++) {
                        float v = s[mi][nj][rr*2+e] + al[nj][e];
                        if (diag && (k0 + wn*64 + nj*8 + (lane&3)*2 + e) > rowg) v = -1e30f;
                        s[mi][nj][rr*2+e] = v;
                        mx = fmaxf(mx, v);
                    }
                }
                mx = fmaxf(mx, __shfl_xor_sync(0xffffffffu, mx, 1));
                mx = fmaxf(mx, __shfl_xor_sync(0xffffffffu, mx, 2));
                if ((lane & 3) == 0) red_mx[wn][rloc] = mx;
            }
        }
        __syncthreads();

        #pragma unroll
        for (int mi = 0; mi < 2; mi++) {
            #pragma unroll
            for (int rr = 0; rr < 2; rr++) {
                const int rloc = rbase + mi * 16 + rr * 8;
                const float mx = fmaxf(red_mx[0][rloc], red_mx[1][rloc]);
                const float mnew = fmaxf(m_[mi][rr], mx);
                const float cr = __expf(m_[mi][rr] - mnew);
                corr[mi][rr] = cr;
                m_[mi][rr] = mnew;
                float ls = 0.f;
                #pragma unroll
                for (int nj = 0; nj < 8; nj++) {
                    #pragma unroll
                    for (int e = 0; e < 2; e++) {
                        float p = __expf(s[mi][nj][rr*2+e] - mnew);
                        s[mi][nj][rr*2+e] = p;
                        ls += p;
                    }
                }
                ls += __shfl_xor_sync(0xffffffffu, ls, 1);
                ls += __shfl_xor_sync(0xffffffffu, ls, 2);
                if ((lane & 3) == 0) red_sm[wn][rloc] = ls;
                #pragma unroll
                for (int nj = 0; nj < 8; nj++) {
                    o[mi][nj][rr*2]   *= cr;
                    o[mi][nj][rr*2+1] *= cr;
                }
            }
        }
        __syncthreads();
        #pragma unroll
        for (int mi = 0; mi < 2; mi++)
            #pragma unroll
            for (int rr = 0; rr < 2; rr++) {
                const int rloc = rbase + mi * 16 + rr * 8;
                l_[mi][rr] = l_[mi][rr] * corr[mi][rr] + red_sm[0][rloc] + red_sm[1][rloc];
            }

        #pragma unroll
        for (int mi = 0; mi < 2; mi++) {
            #pragma unroll
            for (int rr = 0; rr < 2; rr++) {
                const uint32_t roff = (uint32_t)(rbase + mi * 16 + rr * 8) * STR
                                    + (wn * 64 + (lane & 3) * 2) * 2;
                #pragma unroll
                for (int nj = 0; nj < 8; nj++)
                    *(uint32_t*)(Pp + roff + nj * 16) =
                        pack_h(s[mi][nj][rr*2], s[mi][nj][rr*2+1]);
            }
        }
        __syncthreads();

        #pragma unroll
        for (int kk = 0; kk < 8; kk++) {
            uint32_t aH[2][4], bF[4][4];
            ldsm4(aH[0], ph_b + kk * 32);
            ldsm4(aH[1], ph_b + kk * 32 + 16 * STR);
            #pragma unroll
            for (int j2 = 0; j2 < 4; j2++) ldsm4(bF[j2], vh_b + kk * 32 + j2 * 16 * STR);
            #pragma unroll
            for (int mi = 0; mi < 2; mi++)
                #pragma unroll
                for (int j2 = 0; j2 < 4; j2++) {
                    mma16816(o[mi][2*j2],   aH[mi], &bF[j2][0]);
                    mma16816(o[mi][2*j2+1], aH[mi], &bF[j2][2]);
                }
        }
        __syncthreads();
    }

    const int b = bh >> 5, h = bh & 31;
    #pragma unroll
    for (int mi = 0; mi < 2; mi++) {
        #pragma unroll
        for (int rr = 0; rr < 2; rr++) {
            const float invl = 1.f / l_[mi][rr];
            const int srow = q0 + rbase + mi * 16 + rr * 8;
            __half* op = g_ctxh + ((size_t)(b * SEQ + srow)) * HID + h * HD
                       + wn * 64 + (lane & 3) * 2;
            #pragma unroll
            for (int nj = 0; nj < 8; nj++)
                *(uint32_t*)(op + nj * 8) = pack_h(o[mi][nj][rr*2] * invl,
                                                   o[mi][nj][rr*2+1] * invl);
        }
    }
}

// =============================== launch ====================================
extern "C" void kernel_launch(void* const* d_in, const int* in_sizes, int n_in,
                              void* d_out, int out_size)
{
    const float* hs    = (const float*)d_in[0];
    const float* resid = (const float*)d_in[1];
    const float* alibi = (const float*)d_in[2];
    const float* Wqkv  = (const float*)d_in[4];
    const float* bqkv  = (const float*)d_in[5];
    const float* Wd    = (const float*)d_in[6];
    const float* bd    = (const float*)d_in[7];
    float* out = (float*)d_out;

    cudaFuncSetAttribute(gemm_mma_kernel<true>,
                         cudaFuncAttributeMaxDynamicSharedMemorySize, GEMM_SMEM);
    cudaFuncSetAttribute(gemm_mma_kernel<false>,
                         cudaFuncAttributeMaxDynamicSharedMemorySize, GEMM_SMEM);
    cudaFuncSetAttribute(attn_mma_kernel,
                         cudaFuncAttributeMaxDynamicSharedMemorySize, ATT_SMEM);

    __half* d_ah;    cudaGetSymbolAddress((void**)&d_ah,    g_ah);
    __half* d_wqkvT; cudaGetSymbolAddress((void**)&d_wqkvT, g_wqkvT);
    __half* d_wdT;   cudaGetSymbolAddress((void**)&d_wdT,   g_wdT);
    __half* d_ctxh;  cudaGetSymbolAddress((void**)&d_ctxh,  g_ctxh);

    conv_fp16_kernel<<<(MROWS * HID / 4 + 255) / 256, 256>>>(hs, d_ah, MROWS * HID / 4);
    transpose_fp16_kernel<<<dim3(NQKV / 32, HID / 32), dim3(32, 8)>>>(Wqkv, d_wqkvT, HID, NQKV);
    transpose_fp16_kernel<<<dim3(HID / 32, HID / 32), dim3(32, 8)>>>(Wd, d_wdT, HID, HID);

    gemm_mma_kernel<true><<<dim3(NQKV/128, MROWS/256), 512, GEMM_SMEM>>>(d_ah, d_wqkvT, bqkv, nullptr, nullptr);
    attn_mma_kernel<<<dim3(SEQ/128, BATCH*NH), 256, ATT_SMEM>>>(alibi);
    gemm_mma_kernel<false><<<dim3(HID/128, MROWS/256), 512, GEMM_SMEM>>>(d_ctxh, d_wdT, bd, resid, out);
}

// round 11
// speedup vs baseline: 1.6290x; 1.1786x over previous
#include <cuda_runtime.h>
#include <cuda_fp16.h>
#include <stdint.h>

#define HID   4096
#define SEQ   2048
#define BATCH 2
#define NH    32
#define HD    128
#define MROWS (BATCH*SEQ)
#define NQKV  (3*HID)

__device__ __half g_ah  [(size_t)MROWS*HID];
__device__ __half g_wqkvT[(size_t)NQKV*HID];
__device__ __half g_wdT [(size_t)HID*HID];
__device__ __half g_qh  [(size_t)BATCH*NH*SEQ*HD];   // pre-scaled
__device__ __half g_kh  [(size_t)BATCH*NH*SEQ*HD];
__device__ __half g_vT  [(size_t)BATCH*NH*HD*SEQ];   // [bh][d][s]
__device__ __half g_ctxh[(size_t)MROWS*HID];

// ============================ helpers ======================================
__device__ __forceinline__ uint32_t smem_u32(const void* p) {
    uint32_t a;
    asm("{ .reg .u64 t; cvta.to.shared.u64 t, %1; cvt.u32.u64 %0, t; }" : "=r"(a) : "l"(p));
    return a;
}
__device__ __forceinline__ void ldsm4(uint32_t* r, uint32_t addr) {
    asm volatile("ldmatrix.sync.aligned.m8n8.x4.shared.b16 {%0,%1,%2,%3}, [%4];"
                 : "=r"(r[0]), "=r"(r[1]), "=r"(r[2]), "=r"(r[3]) : "r"(addr));
}
__device__ __forceinline__ void mma16816(float* d, const uint32_t* a, const uint32_t* b) {
    asm volatile("mma.sync.aligned.m16n8k16.row.col.f32.f16.f16.f32 "
                 "{%0,%1,%2,%3}, {%4,%5,%6,%7}, {%8,%9}, {%0,%1,%2,%3};"
                 : "+f"(d[0]), "+f"(d[1]), "+f"(d[2]), "+f"(d[3])
                 : "r"(a[0]), "r"(a[1]), "r"(a[2]), "r"(a[3]), "r"(b[0]), "r"(b[1]));
}
__device__ __forceinline__ uint32_t pack_h(float a, float b) {
    __half2 hh = __floats2half2_rn(a, b);
    return *(uint32_t*)&hh;
}
__device__ __forceinline__ void cpa16(uint32_t dst, const void* src) {
    asm volatile("cp.async.cg.shared.global [%0], [%1], 16;" :: "r"(dst), "l"(src));
}
#define CP_COMMIT() asm volatile("cp.async.commit_group;" ::: "memory")
#define CP_WAIT(n)  asm volatile("cp.async.wait_group %0;" :: "n"(n) : "memory")

// ===================== conversion prologue kernels =========================
__global__ void conv_fp16_kernel(const float* __restrict__ src,
                                 __half* __restrict__ dst, int n4)
{
    const int i = blockIdx.x * blockDim.x + threadIdx.x;
    if (i < n4) {
        float4 v = ((const float4*)src)[i];
        uint2 o;
        o.x = pack_h(v.x, v.y);
        o.y = pack_h(v.z, v.w);
        ((uint2*)dst)[i] = o;
    }
}
__global__ void transpose_fp16_kernel(const float* __restrict__ src,
                                      __half* __restrict__ dst, int R, int C)
{
    __shared__ float t[32][33];
    const int x = blockIdx.x * 32 + threadIdx.x;
    const int y0 = blockIdx.y * 32;
    #pragma unroll
    for (int j = 0; j < 4; j++)
        t[threadIdx.y + j * 8][threadIdx.x] = src[(size_t)(y0 + threadIdx.y + j * 8) * C + x];
    __syncthreads();
    const int xo = y0 + threadIdx.x;
    const int yo0 = blockIdx.x * 32;
    #pragma unroll
    for (int j = 0; j < 4; j++)
        dst[(size_t)(yo0 + threadIdx.y + j * 8) * R + xo] =
            __float2half(t[threadIdx.x][threadIdx.y + j * 8]);
}

// == fp16 GEMM: CTA 256x128, 16 warps (4x4), warp 64x32, KCH=64, 3-stage ====
#define KCH    64
#define ROWB   144                 /* 128B data + 16B pad; phase r*9%8 distinct */
#define APLANE (256*ROWB)          /* 36864 */
#define BPLANE (128*ROWB)          /* 18432 */
#define STAGE  (APLANE+BPLANE)     /* 55296 */
#define NSTG   3
#define GEMM_SMEM (NSTG*STAGE)     /* 165888 */

template <bool IS_QKV>
__global__ void __launch_bounds__(512, 1)
gemm_mma_kernel(const __half* __restrict__ Ah, const __half* __restrict__ Wt,
                const float* __restrict__ bias, const float* __restrict__ resid,
                float* __restrict__ out)
{
    constexpr int NC = HID / KCH;   // 64
    extern __shared__ __align__(16) char stg[];
    const uint32_t stg_u = smem_u32(stg);

    const int tid = threadIdx.x;
    const int wid = tid >> 5, lane = tid & 31;
    const int wm  = wid >> 2, wn = wid & 3;      // 4x4 grid, warp tile 64x32
    const int m0  = blockIdx.y * 256, n0 = blockIdx.x * 128;

    // loader: row = tid>>3 (+64i), seg = tid&7 (16B units)
    const int lrow = tid >> 3, lseg = tid & 7;
    const __half* aS = Ah + (size_t)(m0 + lrow) * HID + lseg * 8;
    const __half* bS = Wt + (size_t)(n0 + lrow) * HID + lseg * 8;
    const uint32_t aD = stg_u + lrow * ROWB + lseg * 16;
    const uint32_t bD = stg_u + APLANE + lrow * ROWB + lseg * 16;

    auto issue = [&](int c) {
        const uint32_t off = (uint32_t)(c % NSTG) * STAGE;
        const size_t k0 = (size_t)c * KCH;
        #pragma unroll
        for (int i = 0; i < 4; i++)
            cpa16(aD + off + i * 64 * ROWB, aS + k0 + (size_t)i * 64 * HID);
        #pragma unroll
        for (int i = 0; i < 2; i++)
            cpa16(bD + off + i * 64 * ROWB, bS + k0 + (size_t)i * 64 * HID);
        CP_COMMIT();
    };

    float acc[4][4][4];
    #pragma unroll
    for (int mi = 0; mi < 4; mi++)
        #pragma unroll
        for (int nj = 0; nj < 4; nj++)
            #pragma unroll
            for (int r = 0; r < 4; r++) acc[mi][nj][r] = 0.f;

    const uint32_t a_base = stg_u + (uint32_t)(wm * 64 + (lane & 15)) * ROWB + ((lane >> 4) << 4);
    const uint32_t b_base = stg_u + APLANE
                          + (uint32_t)(wn * 32 + (lane & 7) + ((lane >> 4) << 3)) * ROWB
                          + (((lane >> 3) & 1) << 4);

    issue(0);
    issue(1);

    for (int c = 0; c < NC; c++) {
        CP_WAIT(1);
        __syncthreads();

        const uint32_t soff = (uint32_t)(c % NSTG) * STAGE;
        const uint32_t ab = a_base + soff;
        const uint32_t bb = b_base + soff;
        #pragma unroll
        for (int kk = 0; kk < 4; kk++) {
            uint32_t aH[4][4], bF[2][4];
            #pragma unroll
            for (int mi = 0; mi < 4; mi++) ldsm4(aH[mi], ab + kk * 32 + mi * 16 * ROWB);
            #pragma unroll
            for (int j2 = 0; j2 < 2; j2++) ldsm4(bF[j2], bb + kk * 32 + j2 * 16 * ROWB);
            #pragma unroll
            for (int mi = 0; mi < 4; mi++)
                #pragma unroll
                for (int j2 = 0; j2 < 2; j2++) {
                    mma16816(acc[mi][2*j2],   aH[mi], &bF[j2][0]);
                    mma16816(acc[mi][2*j2+1], aH[mi], &bF[j2][2]);
                }
        }

        if (c + 2 < NC) issue(c + 2);
        else            CP_COMMIT();   // keep group counting aligned
    }

    // ---------------------------- epilogue ---------------------------------
    const float inv_norm = 0.088388347648318447f;
    float b2x[4], b2y[4];
    #pragma unroll
    for (int nj = 0; nj < 4; nj++) {
        const int col = n0 + wn * 32 + nj * 8 + (lane & 3) * 2;
        b2x[nj] = __ldg(&bias[col]);
        b2y[nj] = __ldg(&bias[col + 1]);
    }
    if (IS_QKV) {
        const int h = blockIdx.x / 3, comp = blockIdx.x % 3;
        #pragma unroll
        for (int mi = 0; mi < 4; mi++) {
            #pragma unroll
            for (int rr = 0; rr < 2; rr++) {
                const int row = m0 + wm * 64 + mi * 16 + (lane >> 2) + rr * 8;
                const int bbat = row >> 11, ss = row & 2047;
                #pragma unroll
                for (int nj = 0; nj < 4; nj++) {
                    const int d = wn * 32 + nj * 8 + (lane & 3) * 2;
                    float vx = acc[mi][nj][rr*2]   + b2x[nj];
                    float vy = acc[mi][nj][rr*2+1] + b2y[nj];
                    if (comp == 0) {
                        __half* dst = g_qh + ((size_t)(bbat * NH + h) * SEQ + ss) * HD + d;
                        *(uint32_t*)dst = pack_h(vx * inv_norm, vy * inv_norm);
                    } else if (comp == 1) {
                        __half* dst = g_kh + ((size_t)(bbat * NH + h) * SEQ + ss) * HD + d;
                        *(uint32_t*)dst = pack_h(vx, vy);
                    } else {
                        __half* dst = g_vT + ((size_t)(bbat * NH + h) * HD + d) * SEQ + ss;
                        dst[0]   = __float2half(vx);
                        dst[SEQ] = __float2half(vy);
                    }
                }
            }
        }
    } else {
        #pragma unroll
        for (int mi = 0; mi < 4; mi++) {
            #pragma unroll
            for (int rr = 0; rr < 2; rr++) {
                const int row = m0 + wm * 64 + mi * 16 + (lane >> 2) + rr * 8;
                const size_t o = (size_t)row * HID + n0 + wn * 32 + (lane & 3) * 2;
                #pragma unroll
                for (int nj = 0; nj < 4; nj++) {
                    float2 rv = *(const float2*)(resid + o + nj * 8);
                    *(float2*)(out + o + nj * 8) =
                        make_float2(acc[mi][nj][rr*2] + b2x[nj] + rv.x,
                                    acc[mi][nj][rr*2+1] + b2y[nj] + rv.y);
                }
            }
        }
    }
}

// ============ flash attention: cp.async double-buffered K/V ================
// planes (stride 272B, 128 rows): Q | P | K0 | V0 | K1 | V1
#define STR  272
#define PLN  (128*STR)
#define ATT_SMEM (6*PLN)

__global__ void __launch_bounds__(256, 1) attn_mma_kernel(const float* __restrict__ alibi)
{
    extern __shared__ __align__(16) char sm[];
    char* Qh = sm;
    char* Pp = sm + PLN;
    __shared__ float red_mx[2][128];
    __shared__ float red_sm[2][128];

    const int tid = threadIdx.x;
    const int wid = tid >> 5, lane = tid & 31;
    const int wm = wid >> 1, wn = wid & 1;
    const int qt = gridDim.x - 1 - blockIdx.x;
    const int bh = blockIdx.y;
    const int q0 = qt * 128;

    {
        const int r = tid >> 1, c = (tid & 1) * 64;
        const __half* p = g_qh + ((size_t)bh * SEQ + q0) * HD + (size_t)r * HD + c;
        char* d = Qh + r * STR + c * 2;
        #pragma unroll
        for (int i = 0; i < 8; i++)
            *(uint4*)(d + i * 16) = *(const uint4*)(p + i * 8);
    }

    const __half* kgl = g_kh + (size_t)bh * SEQ * HD;
    const __half* vgl = g_vT + (size_t)bh * HD * SEQ;
    const int lr = tid >> 1, lc = (tid & 1) * 64;
    const uint32_t kdst0 = smem_u32(sm) + 2 * PLN + lr * STR + lc * 2;

    auto issueKV = [&](int kt, int buf) {
        const __half* kp = kgl + (size_t)(kt * 128 + lr) * HD + lc;
        const __half* vp = vgl + (size_t)lr * SEQ + kt * 128 + lc;
        const uint32_t kd = kdst0 + buf * 2 * PLN;
        #pragma unroll
        for (int i = 0; i < 8; i++) {
            cpa16(kd + i * 16, kp + i * 8);
            cpa16(kd + PLN + i * 16, vp + i * 8);
        }
        CP_COMMIT();
    };

    const uint32_t a_off = (uint32_t)(wm * 32 + (lane & 15)) * STR + ((lane >> 4) << 4);
    const uint32_t b_off = (uint32_t)(wn * 64 + (lane & 7) + ((lane >> 4) << 3)) * STR
                         + (((lane >> 3) & 1) << 4);
    const uint32_t qh_b = smem_u32(Qh) + a_off;
    const uint32_t ph_b = smem_u32(Pp) + a_off;

    float o[2][8][4];
    float m_[2][2], l_[2][2], corr[2][2];
    #pragma unroll
    for (int mi = 0; mi < 2; mi++)
        #pragma unroll
        for (int rr = 0; rr < 2; rr++) { m_[mi][rr] = -1e30f; l_[mi][rr] = 0.f; }
    #pragma unroll
    for (int mi = 0; mi < 2; mi++)
        #pragma unroll
        for (int nj = 0; nj < 8; nj++)
            #pragma unroll
            for (int r = 0; r < 4; r++) o[mi][nj][r] = 0.f;

    const float* albase = alibi + (size_t)bh * SEQ;
    const int rbase = wm * 32 + (lane >> 2);

    issueKV(0, 0);

    for (int kt = 0; kt <= qt; kt++) {
        const int cur = kt & 1;
        const bool more = (kt < qt);
        if (more) { issueKV(kt + 1, cur ^ 1); CP_WAIT(1); }
        else      { CP_WAIT(0); }
        __syncthreads();

        const uint32_t kh_b = smem_u32(sm) + (2 + 2 * cur) * PLN + b_off;
        const uint32_t vh_b = kh_b + PLN;
        const int k0 = kt * 128;

        float s[2][8][4];
        #pragma unroll
        for (int mi = 0; mi < 2; mi++)
            #pragma unroll
            for (int nj = 0; nj < 8; nj++)
                #pragma unroll
                for (int r = 0; r < 4; r++) s[mi][nj][r] = 0.f;
        #pragma unroll
        for (int kk = 0; kk < 8; kk++) {
            uint32_t aH[2][4], bF[4][4];
            ldsm4(aH[0], qh_b + kk * 32);
            ldsm4(aH[1], qh_b + kk * 32 + 16 * STR);
            #pragma unroll
            for (int j2 = 0; j2 < 4; j2++) ldsm4(bF[j2], kh_b + kk * 32 + j2 * 16 * STR);
            #pragma unroll
            for (int mi = 0; mi < 2; mi++)
                #pragma unroll
                for (int j2 = 0; j2 < 4; j2++) {
                    mma16816(s[mi][2*j2],   aH[mi], &bF[j2][0]);
                    mma16816(s[mi][2*j2+1], aH[mi], &bF[j2][2]);
                }
        }

        float al[8][2];
        #pragma unroll
        for (int nj = 0; nj < 8; nj++) {
            const int col = k0 + wn * 64 + nj * 8 + (lane & 3) * 2;
            al[nj][0] = __ldg(albase + col);
            al[nj][1] = __ldg(albase + col + 1);
        }
        const bool diag = (kt == qt);
        #pragma unroll
        for (int mi = 0; mi < 2; mi++) {
            #pragma unroll
            for (int rr = 0; rr < 2; rr++) {
                const int rloc = rbase + mi * 16 + rr * 8;
                const int rowg = q0 + rloc;
                float mx = -1e30f;
                #pragma unroll
                for (int nj = 0; nj < 8; nj++) {
                    #pragma unroll
                    for (int e = 0; e < 2; e++) {
                        float v = s[mi][nj][rr*2+e] + al[nj][e];
                        if (diag && (k0 + wn*64 + nj*8 + (lane&3)*2 + e) > rowg) v = -1e30f;
                        s[mi][nj][rr*2+e] = v;
                        mx = fmaxf(mx, v);
                    }
                }
                mx = fmaxf(mx, __shfl_xor_sync(0xffffffffu, mx, 1));
                mx = fmaxf(mx, __shfl_xor_sync(0xffffffffu, mx, 2));
                if ((lane & 3) == 0) red_mx[wn][rloc] = mx;
            }
        }
        __syncthreads();

        #pragma unroll
        for (int mi = 0; mi < 2; mi++) {
            #pragma unroll
            for (int rr = 0; rr < 2; rr++) {
                const int rloc = rbase + mi * 16 + rr * 8;
                const float mx = fmaxf(red_mx[0][rloc], red_mx[1][rloc]);
                const float mnew = fmaxf(m_[mi][rr], mx);
                const float cr = __expf(m_[mi][rr] - mnew);
                corr[mi][rr] = cr;
                m_[mi][rr] = mnew;
                float ls = 0.f;
                #pragma unroll
                for (int nj = 0; nj < 8; nj++) {
                    #pragma unroll
                    for (int e = 0; e < 2; e++) {
                        float p = __expf(s[mi][nj][rr*2+e] - mnew);
                        s[mi][nj][rr*2+e] = p;
                        ls += p;
                    }
                }
                ls += __shfl_xor_sync(0xffffffffu, ls, 1);
                ls += __shfl_xor_sync(0xffffffffu, ls, 2);
                if ((lane & 3) == 0) red_sm[wn][rloc] = ls;
                #pragma unroll
                for (int nj = 0; nj < 8; nj++) {
                    o[mi][nj][rr*2]   *= cr;
                    o[mi][nj][rr*2+1] *= cr;
                }
            }
        }
        __syncthreads();
        #pragma unroll
        for (int mi = 0; mi < 2; mi++)
            #pragma unroll
            for (int rr = 0; rr < 2; rr++) {
                const int rloc = rbase + mi * 16 + rr * 8;
                l_[mi][rr] = l_[mi][rr] * corr[mi][rr] + red_sm[0][rloc] + red_sm[1][rloc];
            }

        #pragma unroll
        for (int mi = 0; mi < 2; mi++) {
            #pragma unroll
            for (int rr = 0; rr < 2; rr++) {
                const uint32_t roff = (uint32_t)(rbase + mi * 16 + rr * 8) * STR
                                    + (wn * 64 + (lane & 3) * 2) * 2;
                #pragma unroll
                for (int nj = 0; nj < 8; nj++)
                    *(uint32_t*)(Pp + roff + nj * 16) =
                        pack_h(s[mi][nj][rr*2], s[mi][nj][rr*2+1]);
            }
        }
        __syncthreads();

        #pragma unroll
        for (int kk = 0; kk < 8; kk++) {
            uint32_t aH[2][4], bF[4][4];
            ldsm4(aH[0], ph_b + kk * 32);
            ldsm4(aH[1], ph_b + kk * 32 + 16 * STR);
            #pragma unroll
            for (int j2 = 0; j2 < 4; j2++) ldsm4(bF[j2], vh_b + kk * 32 + j2 * 16 * STR);
            #pragma unroll
            for (int mi = 0; mi < 2; mi++)
                #pragma unroll
                for (int j2 = 0; j2 < 4; j2++) {
                    mma16816(o[mi][2*j2],   aH[mi], &bF[j2][0]);
                    mma16816(o[mi][2*j2+1], aH[mi], &bF[j2][2]);
                }
        }
        __syncthreads();
    }

    const int b = bh >> 5, h = bh & 31;
    #pragma unroll
    for (int mi = 0; mi < 2; mi++) {
        #pragma unroll
        for (int rr = 0; rr < 2; rr++) {
            const float invl = 1.f / l_[mi][rr];
            const int srow = q0 + rbase + mi * 16 + rr * 8;
            __half* op = g_ctxh + ((size_t)(b * SEQ + srow)) * HID + h * HD
                       + wn * 64 + (lane & 3) * 2;
            #pragma unroll
            for (int nj = 0; nj < 8; nj++)
                *(uint32_t*)(op + nj * 8) = pack_h(o[mi][nj][rr*2] * invl,
                                                   o[mi][nj][rr*2+1] * invl);
        }
    }
}

// =============================== launch ====================================
extern "C" void kernel_launch(void* const* d_in, const int* in_sizes, int n_in,
                              void* d_out, int out_size)
{
    const float* hs    = (const float*)d_in[0];
    const float* resid = (const float*)d_in[1];
    const float* alibi = (const float*)d_in[2];
    const float* Wqkv  = (const float*)d_in[4];
    const float* bqkv  = (const float*)d_in[5];
    const float* Wd    = (const float*)d_in[6];
    const float* bd    = (const float*)d_in[7];
    float* out = (float*)d_out;

    cudaFuncSetAttribute(gemm_mma_kernel<true>,
                         cudaFuncAttributeMaxDynamicSharedMemorySize, GEMM_SMEM);
    cudaFuncSetAttribute(gemm_mma_kernel<false>,
                         cudaFuncAttributeMaxDynamicSharedMemorySize, GEMM_SMEM);
    cudaFuncSetAttribute(attn_mma_kernel,
                         cudaFuncAttributeMaxDynamicSharedMemorySize, ATT_SMEM);

    __half* d_ah;    cudaGetSymbolAddress((void**)&d_ah,    g_ah);
    __half* d_wqkvT; cudaGetSymbolAddress((void**)&d_wqkvT, g_wqkvT);
    __half* d_wdT;   cudaGetSymbolAddress((void**)&d_wdT,   g_wdT);
    __half* d_ctxh;  cudaGetSymbolAddress((void**)&d_ctxh,  g_ctxh);

    conv_fp16_kernel<<<(MROWS * HID / 4 + 255) / 256, 256>>>(hs, d_ah, MROWS * HID / 4);
    transpose_fp16_kernel<<<dim3(NQKV / 32, HID / 32), dim3(32, 8)>>>(Wqkv, d_wqkvT, HID, NQKV);
    transpose_fp16_kernel<<<dim3(HID / 32, HID / 32), dim3(32, 8)>>>(Wd, d_wdT, HID, HID);

    gemm_mma_kernel<true><<<dim3(NQKV/128, MROWS/256), 512, GEMM_SMEM>>>(d_ah, d_wqkvT, bqkv, nullptr, nullptr);
    attn_mma_kernel<<<dim3(SEQ/128, BATCH*NH), 256, ATT_SMEM>>>(alibi);
    gemm_mma_kernel<false><<<dim3(HID/128, MROWS/256), 512, GEMM_SMEM>>>(d_ctxh, d_wdT, bd, resid, out);
}

// round 12
// speedup vs baseline: 1.6478x; 1.0115x over previous
#include <cuda_runtime.h>
#include <cuda_fp16.h>
#include <stdint.h>

#define HID   4096
#define SEQ   2048
#define BATCH 2
#define NH    32
#define HD    128
#define MROWS (BATCH*SEQ)
#define NQKV  (3*HID)

__device__ __half g_ah  [(size_t)MROWS*HID];
__device__ __half g_wqkvT[(size_t)NQKV*HID];
__device__ __half g_wdT [(size_t)HID*HID];
__device__ __half g_qh  [(size_t)BATCH*NH*SEQ*HD];   // pre-scaled
__device__ __half g_kh  [(size_t)BATCH*NH*SEQ*HD];
__device__ __half g_vT  [(size_t)BATCH*NH*HD*SEQ];   // [bh][d][s]
__device__ __half g_ctxh[(size_t)MROWS*HID];

// ============================ helpers ======================================
__device__ __forceinline__ uint32_t smem_u32(const void* p) {
    uint32_t a;
    asm("{ .reg .u64 t; cvta.to.shared.u64 t, %1; cvt.u32.u64 %0, t; }" : "=r"(a) : "l"(p));
    return a;
}
__device__ __forceinline__ void ldsm4(uint32_t* r, uint32_t addr) {
    asm volatile("ldmatrix.sync.aligned.m8n8.x4.shared.b16 {%0,%1,%2,%3}, [%4];"
                 : "=r"(r[0]), "=r"(r[1]), "=r"(r[2]), "=r"(r[3]) : "r"(addr));
}
__device__ __forceinline__ void mma16816(float* d, const uint32_t* a, const uint32_t* b) {
    asm volatile("mma.sync.aligned.m16n8k16.row.col.f32.f16.f16.f32 "
                 "{%0,%1,%2,%3}, {%4,%5,%6,%7}, {%8,%9}, {%0,%1,%2,%3};"
                 : "+f"(d[0]), "+f"(d[1]), "+f"(d[2]), "+f"(d[3])
                 : "r"(a[0]), "r"(a[1]), "r"(a[2]), "r"(a[3]), "r"(b[0]), "r"(b[1]));
}
__device__ __forceinline__ uint32_t pack_h(float a, float b) {
    __half2 hh = __floats2half2_rn(a, b);
    return *(uint32_t*)&hh;
}
__device__ __forceinline__ void cpa16(uint32_t dst, const void* src) {
    asm volatile("cp.async.cg.shared.global [%0], [%1], 16;" :: "r"(dst), "l"(src));
}
#define CP_COMMIT() asm volatile("cp.async.commit_group;" ::: "memory")
#define CP_WAIT(n)  asm volatile("cp.async.wait_group %0;" :: "n"(n) : "memory")

// ===================== conversion prologue kernels =========================
__global__ void conv_fp16_kernel(const float* __restrict__ src,
                                 __half* __restrict__ dst, int n4)
{
    const int i = blockIdx.x * blockDim.x + threadIdx.x;
    if (i < n4) {
        float4 v = ((const float4*)src)[i];
        uint2 o;
        o.x = pack_h(v.x, v.y);
        o.y = pack_h(v.z, v.w);
        ((uint2*)dst)[i] = o;
    }
}
__global__ void transpose_fp16_kernel(const float* __restrict__ src,
                                      __half* __restrict__ dst, int R, int C)
{
    __shared__ float t[32][33];
    const int x = blockIdx.x * 32 + threadIdx.x;
    const int y0 = blockIdx.y * 32;
    #pragma unroll
    for (int j = 0; j < 4; j++)
        t[threadIdx.y + j * 8][threadIdx.x] = src[(size_t)(y0 + threadIdx.y + j * 8) * C + x];
    __syncthreads();
    const int xo = y0 + threadIdx.x;
    const int yo0 = blockIdx.x * 32;
    #pragma unroll
    for (int j = 0; j < 4; j++)
        dst[(size_t)(yo0 + threadIdx.y + j * 8) * R + xo] =
            __float2half(t[threadIdx.x][threadIdx.y + j * 8]);
}

// == fp16 GEMM: CTA 256x128, 16 warps (4x4), warp 64x32, KCH=64, 4-stage ====
#define KCH    64
#define ROWB   144
#define APLANE (256*ROWB)
#define BPLANE (128*ROWB)
#define STAGE  (APLANE+BPLANE)     /* 55296 */
#define NSTG   4
#define GEMM_SMEM (NSTG*STAGE)     /* 221184 */

template <bool IS_QKV>
__global__ void __launch_bounds__(512, 1)
gemm_mma_kernel(const __half* __restrict__ Ah, const __half* __restrict__ Wt,
                const float* __restrict__ bias, const float* __restrict__ resid,
                float* __restrict__ out)
{
    constexpr int NC = HID / KCH;   // 64
    extern __shared__ __align__(16) char stg[];
    const uint32_t stg_u = smem_u32(stg);

    const int tid = threadIdx.x;
    const int wid = tid >> 5, lane = tid & 31;
    const int wm  = wid >> 2, wn = wid & 3;
    const int m0  = blockIdx.y * 256, n0 = blockIdx.x * 128;

    const int lrow = tid >> 3, lseg = tid & 7;
    const __half* aS = Ah + (size_t)(m0 + lrow) * HID + lseg * 8;
    const __half* bS = Wt + (size_t)(n0 + lrow) * HID + lseg * 8;
    const uint32_t aD = stg_u + lrow * ROWB + lseg * 16;
    const uint32_t bD = stg_u + APLANE + lrow * ROWB + lseg * 16;

    auto issue = [&](int c) {
        const uint32_t off = (uint32_t)(c % NSTG) * STAGE;
        const size_t k0 = (size_t)c * KCH;
        #pragma unroll
        for (int i = 0; i < 4; i++)
            cpa16(aD + off + i * 64 * ROWB, aS + k0 + (size_t)i * 64 * HID);
        #pragma unroll
        for (int i = 0; i < 2; i++)
            cpa16(bD + off + i * 64 * ROWB, bS + k0 + (size_t)i * 64 * HID);
        CP_COMMIT();
    };

    float acc[4][4][4];
    #pragma unroll
    for (int mi = 0; mi < 4; mi++)
        #pragma unroll
        for (int nj = 0; nj < 4; nj++)
            #pragma unroll
            for (int r = 0; r < 4; r++) acc[mi][nj][r] = 0.f;

    const uint32_t a_base = stg_u + (uint32_t)(wm * 64 + (lane & 15)) * ROWB + ((lane >> 4) << 4);
    const uint32_t b_base = stg_u + APLANE
                          + (uint32_t)(wn * 32 + (lane & 7) + ((lane >> 4) << 3)) * ROWB
                          + (((lane >> 3) & 1) << 4);

    issue(0); issue(1); issue(2);

    for (int c = 0; c < NC; c++) {
        CP_WAIT(2);
        __syncthreads();

        const uint32_t soff = (uint32_t)(c % NSTG) * STAGE;
        const uint32_t ab = a_base + soff;
        const uint32_t bb = b_base + soff;
        #pragma unroll
        for (int kk = 0; kk < 4; kk++) {
            uint32_t aH[4][4], bF[2][4];
            #pragma unroll
            for (int mi = 0; mi < 4; mi++) ldsm4(aH[mi], ab + kk * 32 + mi * 16 * ROWB);
            #pragma unroll
            for (int j2 = 0; j2 < 2; j2++) ldsm4(bF[j2], bb + kk * 32 + j2 * 16 * ROWB);
            #pragma unroll
            for (int mi = 0; mi < 4; mi++)
                #pragma unroll
                for (int j2 = 0; j2 < 2; j2++) {
                    mma16816(acc[mi][2*j2],   aH[mi], &bF[j2][0]);
                    mma16816(acc[mi][2*j2+1], aH[mi], &bF[j2][2]);
                }
        }

        if (c + 3 < NC) issue(c + 3);
        else            CP_COMMIT();
    }

    // ---------------------------- epilogue ---------------------------------
    const float inv_norm = 0.088388347648318447f;
    float b2x[4], b2y[4];
    #pragma unroll
    for (int nj = 0; nj < 4; nj++) {
        const int col = n0 + wn * 32 + nj * 8 + (lane & 3) * 2;
        b2x[nj] = __ldg(&bias[col]);
        b2y[nj] = __ldg(&bias[col + 1]);
    }
    if (IS_QKV) {
        const int h = blockIdx.x / 3, comp = blockIdx.x % 3;
        #pragma unroll
        for (int mi = 0; mi < 4; mi++) {
            #pragma unroll
            for (int rr = 0; rr < 2; rr++) {
                const int row = m0 + wm * 64 + mi * 16 + (lane >> 2) + rr * 8;
                const int bbat = row >> 11, ss = row & 2047;
                #pragma unroll
                for (int nj = 0; nj < 4; nj++) {
                    const int d = wn * 32 + nj * 8 + (lane & 3) * 2;
                    float vx = acc[mi][nj][rr*2]   + b2x[nj];
                    float vy = acc[mi][nj][rr*2+1] + b2y[nj];
                    if (comp == 0) {
                        __half* dst = g_qh + ((size_t)(bbat * NH + h) * SEQ + ss) * HD + d;
                        *(uint32_t*)dst = pack_h(vx * inv_norm, vy * inv_norm);
                    } else if (comp == 1) {
                        __half* dst = g_kh + ((size_t)(bbat * NH + h) * SEQ + ss) * HD + d;
                        *(uint32_t*)dst = pack_h(vx, vy);
                    } else {
                        __half* dst = g_vT + ((size_t)(bbat * NH + h) * HD + d) * SEQ + ss;
                        dst[0]   = __float2half(vx);
                        dst[SEQ] = __float2half(vy);
                    }
                }
            }
        }
    } else {
        #pragma unroll
        for (int mi = 0; mi < 4; mi++) {
            #pragma unroll
            for (int rr = 0; rr < 2; rr++) {
                const int row = m0 + wm * 64 + mi * 16 + (lane >> 2) + rr * 8;
                const size_t o = (size_t)row * HID + n0 + wn * 32 + (lane & 3) * 2;
                #pragma unroll
                for (int nj = 0; nj < 4; nj++) {
                    float2 rv = *(const float2*)(resid + o + nj * 8);
                    *(float2*)(out + o + nj * 8) =
                        make_float2(acc[mi][nj][rr*2] + b2x[nj] + rv.x,
                                    acc[mi][nj][rr*2+1] + b2y[nj] + rv.y);
                }
            }
        }
    }
}

// ======= flash attention: 8 warps x (16 rows x 128 cols), warp-local softmax
// planes (stride 272B, 128 rows): Q | P | K0 | V0 | K1 | V1
#define STR  272
#define PLN  (128*STR)
#define ATT_SMEM (6*PLN)

__global__ void __launch_bounds__(256, 1) attn_mma_kernel(const float* __restrict__ alibi)
{
    extern __shared__ __align__(16) char sm[];
    char* Qh = sm;
    char* Pp = sm + PLN;

    const int tid = threadIdx.x;
    const int wid = tid >> 5, lane = tid & 31;
    const int qt = gridDim.x - 1 - blockIdx.x;
    const int bh = blockIdx.y;
    const int q0 = qt * 128;

    // Q plain copy (pre-scaled fp16)
    {
        const int r = tid >> 1, c = (tid & 1) * 64;
        const __half* p = g_qh + ((size_t)bh * SEQ + q0) * HD + (size_t)r * HD + c;
        char* d = Qh + r * STR + c * 2;
        #pragma unroll
        for (int i = 0; i < 8; i++)
            *(uint4*)(d + i * 16) = *(const uint4*)(p + i * 8);
    }

    const __half* kgl = g_kh + (size_t)bh * SEQ * HD;
    const __half* vgl = g_vT + (size_t)bh * HD * SEQ;
    const int lr = tid >> 1, lc = (tid & 1) * 64;
    const uint32_t kdst0 = smem_u32(sm) + 2 * PLN + lr * STR + lc * 2;

    auto issueKV = [&](int kt, int buf) {
        const __half* kp = kgl + (size_t)(kt * 128 + lr) * HD + lc;
        const __half* vp = vgl + (size_t)lr * SEQ + kt * 128 + lc;
        const uint32_t kd = kdst0 + buf * 2 * PLN;
        #pragma unroll
        for (int i = 0; i < 8; i++) {
            cpa16(kd + i * 16, kp + i * 8);
            cpa16(kd + PLN + i * 16, vp + i * 8);
        }
        CP_COMMIT();
    };

    // warp owns rows wid*16..+15
    const uint32_t a_off = (uint32_t)(wid * 16 + (lane & 15)) * STR + ((lane >> 4) << 4);
    const uint32_t b_off = (uint32_t)((lane & 7) + ((lane >> 4) << 3)) * STR
                         + (((lane >> 3) & 1) << 4);
    const uint32_t qh_b = smem_u32(Qh) + a_off;
    const uint32_t ph_b = smem_u32(Pp) + a_off;

    float o[16][4];
    float m_[2], l_[2];
    m_[0] = m_[1] = -1e30f; l_[0] = l_[1] = 0.f;
    #pragma unroll
    for (int nj = 0; nj < 16; nj++)
        #pragma unroll
        for (int r = 0; r < 4; r++) o[nj][r] = 0.f;

    const float* albase = alibi + (size_t)bh * SEQ;
    const int rq = lane >> 2, cq = (lane & 3) * 2;

    issueKV(0, 0);

    for (int kt = 0; kt <= qt; kt++) {
        const int cur = kt & 1;
        if (kt < qt) { issueKV(kt + 1, cur ^ 1); CP_WAIT(1); }
        else         { CP_WAIT(0); }
        __syncthreads();   // group kt visible to all; prev-iter reads done

        const uint32_t kb = smem_u32(sm) + (2 + 2 * cur) * PLN + b_off;
        const uint32_t vb = kb + PLN;
        const int k0 = kt * 128;

        // ---- S = Q K^T ----
        float s[16][4];
        #pragma unroll
        for (int nj = 0; nj < 16; nj++)
            #pragma unroll
            for (int r = 0; r < 4; r++) s[nj][r] = 0.f;
        #pragma unroll
        for (int kk = 0; kk < 8; kk++) {
            uint32_t aH[4], bF[8][4];
            ldsm4(aH, qh_b + kk * 32);
            #pragma unroll
            for (int j2 = 0; j2 < 8; j2++) ldsm4(bF[j2], kb + kk * 32 + j2 * 16 * STR);
            #pragma unroll
            for (int j2 = 0; j2 < 8; j2++) {
                mma16816(s[2*j2],   aH, &bF[j2][0]);
                mma16816(s[2*j2+1], aH, &bF[j2][2]);
            }
        }

        // ---- alibi + causal + warp-local softmax ----
        const bool diag = (kt == qt);
        float al[16][2];
        #pragma unroll
        for (int nj = 0; nj < 16; nj++) {
            const int col = k0 + nj * 8 + cq;
            al[nj][0] = __ldg(albase + col);
            al[nj][1] = __ldg(albase + col + 1);
        }
        #pragma unroll
        for (int rr = 0; rr < 2; rr++) {
            const int rloc = wid * 16 + rq + rr * 8;
            const int rowg = q0 + rloc;
            float mx = -1e30f;
            #pragma unroll
            for (int nj = 0; nj < 16; nj++) {
                #pragma unroll
                for (int e = 0; e < 2; e++) {
                    float v = s[nj][rr*2+e] + al[nj][e];
                    if (diag && (k0 + nj*8 + cq + e) > rowg) v = -1e30f;
                    s[nj][rr*2+e] = v;
                    mx = fmaxf(mx, v);
                }
            }
            mx = fmaxf(mx, __shfl_xor_sync(0xffffffffu, mx, 1));
            mx = fmaxf(mx, __shfl_xor_sync(0xffffffffu, mx, 2));
            const float mnew = fmaxf(m_[rr], mx);
            const float cr = __expf(m_[rr] - mnew);
            m_[rr] = mnew;
            float ls = 0.f;
            #pragma unroll
            for (int nj = 0; nj < 16; nj++) {
                #pragma unroll
                for (int e = 0; e < 2; e++) {
                    float p = __expf(s[nj][rr*2+e] - mnew);
                    s[nj][rr*2+e] = p;
                    ls += p;
                }
            }
            ls += __shfl_xor_sync(0xffffffffu, ls, 1);
            ls += __shfl_xor_sync(0xffffffffu, ls, 2);
            l_[rr] = l_[rr] * cr + ls;
            #pragma unroll
            for (int nj = 0; nj < 16; nj++) {
                o[nj][rr*2]   *= cr;
                o[nj][rr*2+1] *= cr;
            }
            // write P row (warp-private rows)
            const uint32_t roff = (uint32_t)rloc * STR + cq * 2;
            #pragma unroll
            for (int nj = 0; nj < 16; nj++)
                *(uint32_t*)(Pp + roff + nj * 16) =
                    pack_h(s[nj][rr*2], s[nj][rr*2+1]);
        }
        __syncwarp();   // P rows visible within warp for ldsm

        // ---- O += P V ----
        #pragma unroll
        for (int kk = 0; kk < 8; kk++) {
            uint32_t aP[4], bF[8][4];
            ldsm4(aP, ph_b + kk * 32);
            #pragma unroll
            for (int j2 = 0; j2 < 8; j2++) ldsm4(bF[j2], vb + kk * 32 + j2 * 16 * STR);
            #pragma unroll
            for (int j2 = 0; j2 < 8; j2++) {
                mma16816(o[2*j2],   aP, &bF[j2][0]);
                mma16816(o[2*j2+1], aP, &bF[j2][2]);
            }
        }
        __syncthreads();   // all done reading K/V cur before it is reissued
    }

    // ---- epilogue -> fp16 ctx ----
    const int b = bh >> 5, h = bh & 31;
    #pragma unroll
    for (int rr = 0; rr < 2; rr++) {
        const float invl = 1.f / l_[rr];
        const int srow = q0 + wid * 16 + rq + rr * 8;
        __half* op = g_ctxh + ((size_t)(b * SEQ + srow)) * HID + h * HD + cq;
        #pragma unroll
        for (int nj = 0; nj < 16; nj++)
            *(uint32_t*)(op + nj * 8) = pack_h(o[nj][rr*2] * invl,
                                               o[nj][rr*2+1] * invl);
    }
}

// =============================== launch ====================================
extern "C" void kernel_launch(void* const* d_in, const int* in_sizes, int n_in,
                              void* d_out, int out_size)
{
    const float* hs    = (const float*)d_in[0];
    const float* resid = (const float*)d_in[1];
    const float* alibi = (const float*)d_in[2];
    const float* Wqkv  = (const float*)d_in[4];
    const float* bqkv  = (const float*)d_in[5];
    const float* Wd    = (const float*)d_in[6];
    const float* bd    = (const float*)d_in[7];
    float* out = (float*)d_out;

    cudaFuncSetAttribute(gemm_mma_kernel<true>,
                         cudaFuncAttributeMaxDynamicSharedMemorySize, GEMM_SMEM);
    cudaFuncSetAttribute(gemm_mma_kernel<false>,
                         cudaFuncAttributeMaxDynamicSharedMemorySize, GEMM_SMEM);
    cudaFuncSetAttribute(attn_mma_kernel,
                         cudaFuncAttributeMaxDynamicSharedMemorySize, ATT_SMEM);

    __half* d_ah;    cudaGetSymbolAddress((void**)&d_ah,    g_ah);
    __half* d_wqkvT; cudaGetSymbolAddress((void**)&d_wqkvT, g_wqkvT);
    __half* d_wdT;   cudaGetSymbolAddress((void**)&d_wdT,   g_wdT);
    __half* d_ctxh;  cudaGetSymbolAddress((void**)&d_ctxh,  g_ctxh);

    conv_fp16_kernel<<<(MROWS * HID / 4 + 255) / 256, 256>>>(hs, d_ah, MROWS * HID / 4);
    transpose_fp16_kernel<<<dim3(NQKV / 32, HID / 32), dim3(32, 8)>>>(Wqkv, d_wqkvT, HID, NQKV);
    transpose_fp16_kernel<<<dim3(HID / 32, HID / 32), dim3(32, 8)>>>(Wd, d_wdT, HID, HID);

    gemm_mma_kernel<true><<<dim3(NQKV/128, MROWS/256), 512, GEMM_SMEM>>>(d_ah, d_wqkvT, bqkv, nullptr, nullptr);
    attn_mma_kernel<<<dim3(SEQ/128, BATCH*NH), 256, ATT_SMEM>>>(alibi);
    gemm_mma_kernel<false><<<dim3(HID/128, MROWS/256), 512, GEMM_SMEM>>>(d_ctxh, d_wdT, bd, resid, out);
}

// round 13
// speedup vs baseline: 1.6559x; 1.0049x over previous
#include <cuda_runtime.h>
#include <cuda_fp16.h>
#include <stdint.h>

#define HID   4096
#define SEQ   2048
#define BATCH 2
#define NH    32
#define HD    128
#define MROWS (BATCH*SEQ)
#define NQKV  (3*HID)

__device__ __half g_ah  [(size_t)MROWS*HID];
__device__ __half g_wqkvT[(size_t)NQKV*HID];
__device__ __half g_wdT [(size_t)HID*HID];
__device__ __half g_qh  [(size_t)BATCH*NH*SEQ*HD];   // pre-scaled
__device__ __half g_kh  [(size_t)BATCH*NH*SEQ*HD];
__device__ __half g_vT  [(size_t)BATCH*NH*HD*SEQ];   // [bh][d][s]
__device__ __half g_ctxh[(size_t)MROWS*HID];

// ============================ helpers ======================================
__device__ __forceinline__ uint32_t smem_u32(const void* p) {
    uint32_t a;
    asm("{ .reg .u64 t; cvta.to.shared.u64 t, %1; cvt.u32.u64 %0, t; }" : "=r"(a) : "l"(p));
    return a;
}
__device__ __forceinline__ void ldsm4(uint32_t* r, uint32_t addr) {
    asm volatile("ldmatrix.sync.aligned.m8n8.x4.shared.b16 {%0,%1,%2,%3}, [%4];"
                 : "=r"(r[0]), "=r"(r[1]), "=r"(r[2]), "=r"(r[3]) : "r"(addr));
}
__device__ __forceinline__ void mma16816(float* d, const uint32_t* a, const uint32_t* b) {
    asm volatile("mma.sync.aligned.m16n8k16.row.col.f32.f16.f16.f32 "
                 "{%0,%1,%2,%3}, {%4,%5,%6,%7}, {%8,%9}, {%0,%1,%2,%3};"
                 : "+f"(d[0]), "+f"(d[1]), "+f"(d[2]), "+f"(d[3])
                 : "r"(a[0]), "r"(a[1]), "r"(a[2]), "r"(a[3]), "r"(b[0]), "r"(b[1]));
}
__device__ __forceinline__ uint32_t pack_h(float a, float b) {
    __half2 hh = __floats2half2_rn(a, b);
    return *(uint32_t*)&hh;
}
__device__ __forceinline__ void cpa16(uint32_t dst, const void* src) {
    asm volatile("cp.async.cg.shared.global [%0], [%1], 16;" :: "r"(dst), "l"(src));
}
#define CP_COMMIT() asm volatile("cp.async.commit_group;" ::: "memory")
#define CP_WAIT(n)  asm volatile("cp.async.wait_group %0;" :: "n"(n) : "memory")
#define BARP(id)    asm volatile("bar.sync %0, 64;" :: "r"(id) : "memory")

// ===================== conversion prologue kernels =========================
__global__ void conv_fp16_kernel(const float* __restrict__ src,
                                 __half* __restrict__ dst, int n4)
{
    const int i = blockIdx.x * blockDim.x + threadIdx.x;
    if (i < n4) {
        float4 v = ((const float4*)src)[i];
        uint2 o;
        o.x = pack_h(v.x, v.y);
        o.y = pack_h(v.z, v.w);
        ((uint2*)dst)[i] = o;
    }
}
__global__ void transpose_fp16_kernel(const float* __restrict__ src,
                                      __half* __restrict__ dst, int R, int C)
{
    __shared__ float t[32][33];
    const int x = blockIdx.x * 32 + threadIdx.x;
    const int y0 = blockIdx.y * 32;
    #pragma unroll
    for (int j = 0; j < 4; j++)
        t[threadIdx.y + j * 8][threadIdx.x] = src[(size_t)(y0 + threadIdx.y + j * 8) * C + x];
    __syncthreads();
    const int xo = y0 + threadIdx.x;
    const int yo0 = blockIdx.x * 32;
    #pragma unroll
    for (int j = 0; j < 4; j++)
        dst[(size_t)(yo0 + threadIdx.y + j * 8) * R + xo] =
            __float2half(t[threadIdx.x][threadIdx.y + j * 8]);
}

// == fp16 GEMM: CTA 256x128, 16 warps (4x4), warp 64x32, KCH=64, 4-stage ====
#define KCH    64
#define ROWB   144
#define APLANE (256*ROWB)
#define BPLANE (128*ROWB)
#define STAGE  (APLANE+BPLANE)
#define NSTG   4
#define GEMM_SMEM (NSTG*STAGE)

template <bool IS_QKV>
__global__ void __launch_bounds__(512, 1)
gemm_mma_kernel(const __half* __restrict__ Ah, const __half* __restrict__ Wt,
                const float* __restrict__ bias, const float* __restrict__ resid,
                float* __restrict__ out)
{
    constexpr int NC = HID / KCH;
    extern __shared__ __align__(16) char stg[];
    const uint32_t stg_u = smem_u32(stg);

    const int tid = threadIdx.x;
    const int wid = tid >> 5, lane = tid & 31;
    const int wm  = wid >> 2, wn = wid & 3;
    const int m0  = blockIdx.y * 256, n0 = blockIdx.x * 128;

    const int lrow = tid >> 3, lseg = tid & 7;
    const __half* aS = Ah + (size_t)(m0 + lrow) * HID + lseg * 8;
    const __half* bS = Wt + (size_t)(n0 + lrow) * HID + lseg * 8;
    const uint32_t aD = stg_u + lrow * ROWB + lseg * 16;
    const uint32_t bD = stg_u + APLANE + lrow * ROWB + lseg * 16;

    auto issue = [&](int c) {
        const uint32_t off = (uint32_t)(c % NSTG) * STAGE;
        const size_t k0 = (size_t)c * KCH;
        #pragma unroll
        for (int i = 0; i < 4; i++)
            cpa16(aD + off + i * 64 * ROWB, aS + k0 + (size_t)i * 64 * HID);
        #pragma unroll
        for (int i = 0; i < 2; i++)
            cpa16(bD + off + i * 64 * ROWB, bS + k0 + (size_t)i * 64 * HID);
        CP_COMMIT();
    };

    float acc[4][4][4];
    #pragma unroll
    for (int mi = 0; mi < 4; mi++)
        #pragma unroll
        for (int nj = 0; nj < 4; nj++)
            #pragma unroll
            for (int r = 0; r < 4; r++) acc[mi][nj][r] = 0.f;

    const uint32_t a_base = stg_u + (uint32_t)(wm * 64 + (lane & 15)) * ROWB + ((lane >> 4) << 4);
    const uint32_t b_base = stg_u + APLANE
                          + (uint32_t)(wn * 32 + (lane & 7) + ((lane >> 4) << 3)) * ROWB
                          + (((lane >> 3) & 1) << 4);

    issue(0); issue(1); issue(2);

    for (int c = 0; c < NC; c++) {
        CP_WAIT(2);
        __syncthreads();

        const uint32_t soff = (uint32_t)(c % NSTG) * STAGE;
        const uint32_t ab = a_base + soff;
        const uint32_t bb = b_base + soff;
        #pragma unroll
        for (int kk = 0; kk < 4; kk++) {
            uint32_t aH[4][4], bF[2][4];
            #pragma unroll
            for (int mi = 0; mi < 4; mi++) ldsm4(aH[mi], ab + kk * 32 + mi * 16 * ROWB);
            #pragma unroll
            for (int j2 = 0; j2 < 2; j2++) ldsm4(bF[j2], bb + kk * 32 + j2 * 16 * ROWB);
            #pragma unroll
            for (int mi = 0; mi < 4; mi++)
                #pragma unroll
                for (int j2 = 0; j2 < 2; j2++) {
                    mma16816(acc[mi][2*j2],   aH[mi], &bF[j2][0]);
                    mma16816(acc[mi][2*j2+1], aH[mi], &bF[j2][2]);
                }
        }

        if (c + 3 < NC) issue(c + 3);
        else            CP_COMMIT();
    }

    // epilogue
    const float inv_norm = 0.088388347648318447f;
    float b2x[4], b2y[4];
    #pragma unroll
    for (int nj = 0; nj < 4; nj++) {
        const int col = n0 + wn * 32 + nj * 8 + (lane & 3) * 2;
        b2x[nj] = __ldg(&bias[col]);
        b2y[nj] = __ldg(&bias[col + 1]);
    }
    if (IS_QKV) {
        const int h = blockIdx.x / 3, comp = blockIdx.x % 3;
        #pragma unroll
        for (int mi = 0; mi < 4; mi++) {
            #pragma unroll
            for (int rr = 0; rr < 2; rr++) {
                const int row = m0 + wm * 64 + mi * 16 + (lane >> 2) + rr * 8;
                const int bbat = row >> 11, ss = row & 2047;
                #pragma unroll
                for (int nj = 0; nj < 4; nj++) {
                    const int d = wn * 32 + nj * 8 + (lane & 3) * 2;
                    float vx = acc[mi][nj][rr*2]   + b2x[nj];
                    float vy = acc[mi][nj][rr*2+1] + b2y[nj];
                    if (comp == 0) {
                        __half* dst = g_qh + ((size_t)(bbat * NH + h) * SEQ + ss) * HD + d;
                        *(uint32_t*)dst = pack_h(vx * inv_norm, vy * inv_norm);
                    } else if (comp == 1) {
                        __half* dst = g_kh + ((size_t)(bbat * NH + h) * SEQ + ss) * HD + d;
                        *(uint32_t*)dst = pack_h(vx, vy);
                    } else {
                        __half* dst = g_vT + ((size_t)(bbat * NH + h) * HD + d) * SEQ + ss;
                        dst[0]   = __float2half(vx);
                        dst[SEQ] = __float2half(vy);
                    }
                }
            }
        }
    } else {
        #pragma unroll
        for (int mi = 0; mi < 4; mi++) {
            #pragma unroll
            for (int rr = 0; rr < 2; rr++) {
                const int row = m0 + wm * 64 + mi * 16 + (lane >> 2) + rr * 8;
                const size_t o = (size_t)row * HID + n0 + wn * 32 + (lane & 3) * 2;
                #pragma unroll
                for (int nj = 0; nj < 4; nj++) {
                    float2 rv = *(const float2*)(resid + o + nj * 8);
                    *(float2*)(out + o + nj * 8) =
                        make_float2(acc[mi][nj][rr*2] + b2x[nj] + rv.x,
                                    acc[mi][nj][rr*2+1] + b2y[nj] + rv.y);
                }
            }
        }
    }
}

// ==== flash attention: 4x2 warp grid, pair-scoped named barriers ==========
// planes (stride 272B, 128 rows): Q | P | K0 | V0 | K1 | V1
#define STR  272
#define PLN  (128*STR)
#define ATT_SMEM (6*PLN)

__global__ void __launch_bounds__(256, 1) attn_mma_kernel(const float* __restrict__ alibi)
{
    extern __shared__ __align__(16) char sm[];
    char* Qh = sm;
    char* Pp = sm + PLN;
    __shared__ float red_mx[2][128];
    __shared__ float red_sm[2][128];

    const int tid = threadIdx.x;
    const int wid = tid >> 5, lane = tid & 31;
    const int wm = wid >> 1, wn = wid & 1;
    const int barid = 1 + wm;                 // named barrier per warp pair
    const int qt = gridDim.x - 1 - blockIdx.x;
    const int bh = blockIdx.y;
    const int q0 = qt * 128;

    // Q plain copy (pre-scaled fp16)
    {
        const int r = tid >> 1, c = (tid & 1) * 64;
        const __half* p = g_qh + ((size_t)bh * SEQ + q0) * HD + (size_t)r * HD + c;
        char* d = Qh + r * STR + c * 2;
        #pragma unroll
        for (int i = 0; i < 8; i++)
            *(uint4*)(d + i * 16) = *(const uint4*)(p + i * 8);
    }

    const __half* kgl = g_kh + (size_t)bh * SEQ * HD;
    const __half* vgl = g_vT + (size_t)bh * HD * SEQ;
    const int lr = tid >> 1, lc = (tid & 1) * 64;
    const uint32_t kdst0 = smem_u32(sm) + 2 * PLN + lr * STR + lc * 2;

    auto issueKV = [&](int kt, int buf) {
        const __half* kp = kgl + (size_t)(kt * 128 + lr) * HD + lc;
        const __half* vp = vgl + (size_t)lr * SEQ + kt * 128 + lc;
        const uint32_t kd = kdst0 + buf * 2 * PLN;
        #pragma unroll
        for (int i = 0; i < 8; i++) {
            cpa16(kd + i * 16, kp + i * 8);
            cpa16(kd + PLN + i * 16, vp + i * 8);
        }
        CP_COMMIT();
    };

    const uint32_t a_off = (uint32_t)(wm * 32 + (lane & 15)) * STR + ((lane >> 4) << 4);
    const uint32_t b_off = (uint32_t)(wn * 64 + (lane & 7) + ((lane >> 4) << 3)) * STR
                         + (((lane >> 3) & 1) << 4);
    const uint32_t qh_b = smem_u32(Qh) + a_off;
    const uint32_t ph_b = smem_u32(Pp) + a_off;

    float o[2][8][4];
    float m_[2][2], l_[2][2], corr[2][2];
    #pragma unroll
    for (int mi = 0; mi < 2; mi++)
        #pragma unroll
        for (int rr = 0; rr < 2; rr++) { m_[mi][rr] = -1e30f; l_[mi][rr] = 0.f; }
    #pragma unroll
    for (int mi = 0; mi < 2; mi++)
        #pragma unroll
        for (int nj = 0; nj < 8; nj++)
            #pragma unroll
            for (int r = 0; r < 4; r++) o[mi][nj][r] = 0.f;

    const float* albase = alibi + (size_t)bh * SEQ;
    const int rbase = wm * 32 + (lane >> 2);
    const int cq = (lane & 3) * 2;

    issueKV(0, 0);

    for (int kt = 0; kt <= qt; kt++) {
        const int cur = kt & 1;
        if (kt < qt) { issueKV(kt + 1, cur ^ 1); CP_WAIT(1); }
        else         { CP_WAIT(0); }
        __syncthreads();                       // fills visible to all

        const uint32_t kh_b = smem_u32(sm) + (2 + 2 * cur) * PLN + b_off;
        const uint32_t vh_b = kh_b + PLN;
        const int k0 = kt * 128;

        // ---- S = Q K^T ----
        float s[2][8][4];
        #pragma unroll
        for (int mi = 0; mi < 2; mi++)
            #pragma unroll
            for (int nj = 0; nj < 8; nj++)
                #pragma unroll
                for (int r = 0; r < 4; r++) s[mi][nj][r] = 0.f;
        #pragma unroll
        for (int kk = 0; kk < 8; kk++) {
            uint32_t aH[2][4], bF[4][4];
            ldsm4(aH[0], qh_b + kk * 32);
            ldsm4(aH[1], qh_b + kk * 32 + 16 * STR);
            #pragma unroll
            for (int j2 = 0; j2 < 4; j2++) ldsm4(bF[j2], kh_b + kk * 32 + j2 * 16 * STR);
            #pragma unroll
            for (int mi = 0; mi < 2; mi++)
                #pragma unroll
                for (int j2 = 0; j2 < 4; j2++) {
                    mma16816(s[mi][2*j2],   aH[mi], &bF[j2][0]);
                    mma16816(s[mi][2*j2+1], aH[mi], &bF[j2][2]);
                }
        }

        // ---- alibi + causal + partial row max ----
        float al[8][2];
        #pragma unroll
        for (int nj = 0; nj < 8; nj++) {
            const int col = k0 + wn * 64 + nj * 8 + cq;
            al[nj][0] = __ldg(albase + col);
            al[nj][1] = __ldg(albase + col + 1);
        }
        const bool diag = (kt == qt);
        #pragma unroll
        for (int mi = 0; mi < 2; mi++) {
            #pragma unroll
            for (int rr = 0; rr < 2; rr++) {
                const int rloc = rbase + mi * 16 + rr * 8;
                const int rowg = q0 + rloc;
                float mx = -1e30f;
                #pragma unroll
                for (int nj = 0; nj < 8; nj++) {
                    #pragma unroll
                    for (int e = 0; e < 2; e++) {
                        float v = s[mi][nj][rr*2+e] + al[nj][e];
                        if (diag && (k0 + wn*64 + nj*8 + cq + e) > rowg) v = -1e30f;
                        s[mi][nj][rr*2+e] = v;
                        mx = fmaxf(mx, v);
                    }
                }
                mx = fmaxf(mx, __shfl_xor_sync(0xffffffffu, mx, 1));
                mx = fmaxf(mx, __shfl_xor_sync(0xffffffffu, mx, 2));
                if ((lane & 3) == 0) red_mx[wn][rloc] = mx;
            }
        }
        BARP(barid);                           // pair: maxes exchanged

        // ---- softmax (pair-local) ----
        #pragma unroll
        for (int mi = 0; mi < 2; mi++) {
            #pragma unroll
            for (int rr = 0; rr < 2; rr++) {
                const int rloc = rbase + mi * 16 + rr * 8;
                const float mx = fmaxf(red_mx[0][rloc], red_mx[1][rloc]);
                const float mnew = fmaxf(m_[mi][rr], mx);
                const float cr = __expf(m_[mi][rr] - mnew);
                corr[mi][rr] = cr;
                m_[mi][rr] = mnew;
                float ls = 0.f;
                #pragma unroll
                for (int nj = 0; nj < 8; nj++) {
                    #pragma unroll
                    for (int e = 0; e < 2; e++) {
                        float p = __expf(s[mi][nj][rr*2+e] - mnew);
                        s[mi][nj][rr*2+e] = p;
                        ls += p;
                    }
                }
                ls += __shfl_xor_sync(0xffffffffu, ls, 1);
                ls += __shfl_xor_sync(0xffffffffu, ls, 2);
                if ((lane & 3) == 0) red_sm[wn][rloc] = ls;
                #pragma unroll
                for (int nj = 0; nj < 8; nj++) {
                    o[mi][nj][rr*2]   *= cr;
                    o[mi][nj][rr*2+1] *= cr;
                }
                // write P half-row (pair fills full row)
                const uint32_t roff = (uint32_t)rloc * STR + (wn * 64 + cq) * 2;
                #pragma unroll
                for (int nj = 0; nj < 8; nj++)
                    *(uint32_t*)(Pp + roff + nj * 16) =
                        pack_h(s[mi][nj][rr*2], s[mi][nj][rr*2+1]);
            }
        }
        BARP(barid);                           // pair: sums + P rows ready
        #pragma unroll
        for (int mi = 0; mi < 2; mi++)
            #pragma unroll
            for (int rr = 0; rr < 2; rr++) {
                const int rloc = rbase + mi * 16 + rr * 8;
                l_[mi][rr] = l_[mi][rr] * corr[mi][rr] + red_sm[0][rloc] + red_sm[1][rloc];
            }

        // ---- O += P V ----
        #pragma unroll
        for (int kk = 0; kk < 8; kk++) {
            uint32_t aP[2][4], bF[4][4];
            ldsm4(aP[0], ph_b + kk * 32);
            ldsm4(aP[1], ph_b + kk * 32 + 16 * STR);
            #pragma unroll
            for (int j2 = 0; j2 < 4; j2++) ldsm4(bF[j2], vh_b + kk * 32 + j2 * 16 * STR);
            #pragma unroll
            for (int mi = 0; mi < 2; mi++)
                #pragma unroll
                for (int j2 = 0; j2 < 4; j2++) {
                    mma16816(o[mi][2*j2],   aP[mi], &bF[j2][0]);
                    mma16816(o[mi][2*j2+1], aP[mi], &bF[j2][2]);
                }
        }
        __syncthreads();                       // K/V cur free for reissue
    }

    // ---- epilogue -> fp16 ctx ----
    const int b = bh >> 5, h = bh & 31;
    #pragma unroll
    for (int mi = 0; mi < 2; mi++) {
        #pragma unroll
        for (int rr = 0; rr < 2; rr++) {
            const float invl = 1.f / l_[mi][rr];
            const int srow = q0 + rbase + mi * 16 + rr * 8;
            __half* op = g_ctxh + ((size_t)(b * SEQ + srow)) * HID + h * HD
                       + wn * 64 + cq;
            #pragma unroll
            for (int nj = 0; nj < 8; nj++)
                *(uint32_t*)(op + nj * 8) = pack_h(o[mi][nj][rr*2] * invl,
                                                   o[mi][nj][rr*2+1] * invl);
        }
    }
}

// =============================== launch ====================================
extern "C" void kernel_launch(void* const* d_in, const int* in_sizes, int n_in,
                              void* d_out, int out_size)
{
    const float* hs    = (const float*)d_in[0];
    const float* resid = (const float*)d_in[1];
    const float* alibi = (const float*)d_in[2];
    const float* Wqkv  = (const float*)d_in[4];
    const float* bqkv  = (const float*)d_in[5];
    const float* Wd    = (const float*)d_in[6];
    const float* bd    = (const float*)d_in[7];
    float* out = (float*)d_out;

    cudaFuncSetAttribute(gemm_mma_kernel<true>,
                         cudaFuncAttributeMaxDynamicSharedMemorySize, GEMM_SMEM);
    cudaFuncSetAttribute(gemm_mma_kernel<false>,
                         cudaFuncAttributeMaxDynamicSharedMemorySize, GEMM_SMEM);
    cudaFuncSetAttribute(attn_mma_kernel,
                         cudaFuncAttributeMaxDynamicSharedMemorySize, ATT_SMEM);

    __half* d_ah;    cudaGetSymbolAddress((void**)&d_ah,    g_ah);
    __half* d_wqkvT; cudaGetSymbolAddress((void**)&d_wqkvT, g_wqkvT);
    __half* d_wdT;   cudaGetSymbolAddress((void**)&d_wdT,   g_wdT);
    __half* d_ctxh;  cudaGetSymbolAddress((void**)&d_ctxh,  g_ctxh);

    conv_fp16_kernel<<<(MROWS * HID / 4 + 255) / 256, 256>>>(hs, d_ah, MROWS * HID / 4);
    transpose_fp16_kernel<<<dim3(NQKV / 32, HID / 32), dim3(32, 8)>>>(Wqkv, d_wqkvT, HID, NQKV);
    transpose_fp16_kernel<<<dim3(HID / 32, HID / 32), dim3(32, 8)>>>(Wd, d_wdT, HID, HID);

    gemm_mma_kernel<true><<<dim3(NQKV/128, MROWS/256), 512, GEMM_SMEM>>>(d_ah, d_wqkvT, bqkv, nullptr, nullptr);
    attn_mma_kernel<<<dim3(SEQ/128, BATCH*NH), 256, ATT_SMEM>>>(alibi);
    gemm_mma_kernel<false><<<dim3(HID/128, MROWS/256), 512, GEMM_SMEM>>>(d_ctxh, d_wdT, bd, resid, out);
}

// round 14
// speedup vs baseline: 1.6651x; 1.0056x over previous
#include <cuda_runtime.h>
#include <cuda_fp16.h>
#include <stdint.h>

#define HID   4096
#define SEQ   2048
#define BATCH 2
#define NH    32
#define HD    128
#define MROWS (BATCH*SEQ)
#define NQKV  (3*HID)

__device__ __half g_ah  [(size_t)MROWS*HID];
__device__ __half g_wqkvT[(size_t)NQKV*HID];
__device__ __half g_wdT [(size_t)HID*HID];
__device__ __half g_qh  [(size_t)BATCH*NH*SEQ*HD];   // pre-scaled
__device__ __half g_kh  [(size_t)BATCH*NH*SEQ*HD];
__device__ __half g_vh  [(size_t)BATCH*NH*SEQ*HD];   // [bh][s][d] (same as K)
__device__ __half g_ctxh[(size_t)MROWS*HID];

// ============================ helpers ======================================
__device__ __forceinline__ uint32_t smem_u32(const void* p) {
    uint32_t a;
    asm("{ .reg .u64 t; cvta.to.shared.u64 t, %1; cvt.u32.u64 %0, t; }" : "=r"(a) : "l"(p));
    return a;
}
__device__ __forceinline__ void ldsm4(uint32_t* r, uint32_t addr) {
    asm volatile("ldmatrix.sync.aligned.m8n8.x4.shared.b16 {%0,%1,%2,%3}, [%4];"
                 : "=r"(r[0]), "=r"(r[1]), "=r"(r[2]), "=r"(r[3]) : "r"(addr));
}
__device__ __forceinline__ void ldsm4t(uint32_t* r, uint32_t addr) {
    asm volatile("ldmatrix.sync.aligned.m8n8.x4.trans.shared.b16 {%0,%1,%2,%3}, [%4];"
                 : "=r"(r[0]), "=r"(r[1]), "=r"(r[2]), "=r"(r[3]) : "r"(addr));
}
__device__ __forceinline__ void mma16816(float* d, const uint32_t* a, const uint32_t* b) {
    asm volatile("mma.sync.aligned.m16n8k16.row.col.f32.f16.f16.f32 "
                 "{%0,%1,%2,%3}, {%4,%5,%6,%7}, {%8,%9}, {%0,%1,%2,%3};"
                 : "+f"(d[0]), "+f"(d[1]), "+f"(d[2]), "+f"(d[3])
                 : "r"(a[0]), "r"(a[1]), "r"(a[2]), "r"(a[3]), "r"(b[0]), "r"(b[1]));
}
__device__ __forceinline__ uint32_t pack_h(float a, float b) {
    __half2 hh = __floats2half2_rn(a, b);
    return *(uint32_t*)&hh;
}
__device__ __forceinline__ void cpa16(uint32_t dst, const void* src) {
    asm volatile("cp.async.cg.shared.global [%0], [%1], 16;" :: "r"(dst), "l"(src));
}
#define CP_COMMIT() asm volatile("cp.async.commit_group;" ::: "memory")
#define CP_WAIT(n)  asm volatile("cp.async.wait_group %0;" :: "n"(n) : "memory")
#define BARP(id)    asm volatile("bar.sync %0, 64;" :: "r"(id) : "memory")

// ===================== conversion prologue kernels =========================
__global__ void conv_fp16_kernel(const float* __restrict__ src,
                                 __half* __restrict__ dst, int n4)
{
    const int i = blockIdx.x * blockDim.x + threadIdx.x;
    if (i < n4) {
        float4 v = ((const float4*)src)[i];
        uint2 o;
        o.x = pack_h(v.x, v.y);
        o.y = pack_h(v.z, v.w);
        ((uint2*)dst)[i] = o;
    }
}
__global__ void transpose_fp16_kernel(const float* __restrict__ src,
                                      __half* __restrict__ dst, int R, int C)
{
    __shared__ float t[32][33];
    const int x = blockIdx.x * 32 + threadIdx.x;
    const int y0 = blockIdx.y * 32;
    #pragma unroll
    for (int j = 0; j < 4; j++)
        t[threadIdx.y + j * 8][threadIdx.x] = src[(size_t)(y0 + threadIdx.y + j * 8) * C + x];
    __syncthreads();
    const int xo = y0 + threadIdx.x;
    const int yo0 = blockIdx.x * 32;
    #pragma unroll
    for (int j = 0; j < 4; j++)
        dst[(size_t)(yo0 + threadIdx.y + j * 8) * R + xo] =
            __float2half(t[threadIdx.x][threadIdx.y + j * 8]);
}

// == fp16 GEMM: CTA 256x128, 16 warps (4x4), warp 64x32, KCH=64, 4-stage ====
#define KCH    64
#define ROWB   144
#define APLANE (256*ROWB)
#define BPLANE (128*ROWB)
#define STAGE  (APLANE+BPLANE)
#define NSTG   4
#define GEMM_SMEM (NSTG*STAGE)

template <bool IS_QKV>
__global__ void __launch_bounds__(512, 1)
gemm_mma_kernel(const __half* __restrict__ Ah, const __half* __restrict__ Wt,
                const float* __restrict__ bias, const float* __restrict__ resid,
                float* __restrict__ out)
{
    constexpr int NC = HID / KCH;
    extern __shared__ __align__(16) char stg[];
    const uint32_t stg_u = smem_u32(stg);

    const int tid = threadIdx.x;
    const int wid = tid >> 5, lane = tid & 31;
    const int wm  = wid >> 2, wn = wid & 3;
    const int m0  = blockIdx.y * 256, n0 = blockIdx.x * 128;

    const int lrow = tid >> 3, lseg = tid & 7;
    const __half* aS = Ah + (size_t)(m0 + lrow) * HID + lseg * 8;
    const __half* bS = Wt + (size_t)(n0 + lrow) * HID + lseg * 8;
    const uint32_t aD = stg_u + lrow * ROWB + lseg * 16;
    const uint32_t bD = stg_u + APLANE + lrow * ROWB + lseg * 16;

    auto issue = [&](int c) {
        const uint32_t off = (uint32_t)(c % NSTG) * STAGE;
        const size_t k0 = (size_t)c * KCH;
        #pragma unroll
        for (int i = 0; i < 4; i++)
            cpa16(aD + off + i * 64 * ROWB, aS + k0 + (size_t)i * 64 * HID);
        #pragma unroll
        for (int i = 0; i < 2; i++)
            cpa16(bD + off + i * 64 * ROWB, bS + k0 + (size_t)i * 64 * HID);
        CP_COMMIT();
    };

    float acc[4][4][4];
    #pragma unroll
    for (int mi = 0; mi < 4; mi++)
        #pragma unroll
        for (int nj = 0; nj < 4; nj++)
            #pragma unroll
            for (int r = 0; r < 4; r++) acc[mi][nj][r] = 0.f;

    const uint32_t a_base = stg_u + (uint32_t)(wm * 64 + (lane & 15)) * ROWB + ((lane >> 4) << 4);
    const uint32_t b_base = stg_u + APLANE
                          + (uint32_t)(wn * 32 + (lane & 7) + ((lane >> 4) << 3)) * ROWB
                          + (((lane >> 3) & 1) << 4);

    issue(0); issue(1); issue(2);

    for (int c = 0; c < NC; c++) {
        CP_WAIT(2);
        __syncthreads();

        const uint32_t soff = (uint32_t)(c % NSTG) * STAGE;
        const uint32_t ab = a_base + soff;
        const uint32_t bb = b_base + soff;
        #pragma unroll
        for (int kk = 0; kk < 4; kk++) {
            uint32_t aH[4][4], bF[2][4];
            #pragma unroll
            for (int mi = 0; mi < 4; mi++) ldsm4(aH[mi], ab + kk * 32 + mi * 16 * ROWB);
            #pragma unroll
            for (int j2 = 0; j2 < 2; j2++) ldsm4(bF[j2], bb + kk * 32 + j2 * 16 * ROWB);
            #pragma unroll
            for (int mi = 0; mi < 4; mi++)
                #pragma unroll
                for (int j2 = 0; j2 < 2; j2++) {
                    mma16816(acc[mi][2*j2],   aH[mi], &bF[j2][0]);
                    mma16816(acc[mi][2*j2+1], aH[mi], &bF[j2][2]);
                }
        }

        if (c + 3 < NC) issue(c + 3);
        else            CP_COMMIT();
    }

    // epilogue
    const float inv_norm = 0.088388347648318447f;
    float b2x[4], b2y[4];
    #pragma unroll
    for (int nj = 0; nj < 4; nj++) {
        const int col = n0 + wn * 32 + nj * 8 + (lane & 3) * 2;
        b2x[nj] = __ldg(&bias[col]);
        b2y[nj] = __ldg(&bias[col + 1]);
    }
    if (IS_QKV) {
        const int h = blockIdx.x / 3, comp = blockIdx.x % 3;
        __half* gbase = (comp == 0) ? g_qh : (comp == 1) ? g_kh : g_vh;
        const float scl = (comp == 0) ? inv_norm : 1.f;
        #pragma unroll
        for (int mi = 0; mi < 4; mi++) {
            #pragma unroll
            for (int rr = 0; rr < 2; rr++) {
                const int row = m0 + wm * 64 + mi * 16 + (lane >> 2) + rr * 8;
                const int bbat = row >> 11, ss = row & 2047;
                __half* dstrow = gbase + ((size_t)(bbat * NH + h) * SEQ + ss) * HD;
                #pragma unroll
                for (int nj = 0; nj < 4; nj++) {
                    const int d = wn * 32 + nj * 8 + (lane & 3) * 2;
                    float vx = (acc[mi][nj][rr*2]   + b2x[nj]) * scl;
                    float vy = (acc[mi][nj][rr*2+1] + b2y[nj]) * scl;
                    *(uint32_t*)(dstrow + d) = pack_h(vx, vy);
                }
            }
        }
    } else {
        #pragma unroll
        for (int mi = 0; mi < 4; mi++) {
            #pragma unroll
            for (int rr = 0; rr < 2; rr++) {
                const int row = m0 + wm * 64 + mi * 16 + (lane >> 2) + rr * 8;
                const size_t o = (size_t)row * HID + n0 + wn * 32 + (lane & 3) * 2;
                #pragma unroll
                for (int nj = 0; nj < 4; nj++) {
                    float2 rv = *(const float2*)(resid + o + nj * 8);
                    *(float2*)(out + o + nj * 8) =
                        make_float2(acc[mi][nj][rr*2] + b2x[nj] + rv.x,
                                    acc[mi][nj][rr*2+1] + b2y[nj] + rv.y);
                }
            }
        }
    }
}

// ==== flash attention: 4x2 warps, trans-ldsm V, alibi via slope FMA =======
// planes (stride 272B, 128 rows): Q | P | K0 | V0 | K1 | V1
#define STR  272
#define PLN  (128*STR)
#define ATT_SMEM (6*PLN)

__global__ void __launch_bounds__(256, 1) attn_mma_kernel(const float* __restrict__ alibi)
{
    extern __shared__ __align__(16) char sm[];
    char* Qh = sm;
    char* Pp = sm + PLN;
    __shared__ float red_mx[2][128];
    __shared__ float red_sm[2][128];

    const int tid = threadIdx.x;
    const int wid = tid >> 5, lane = tid & 31;
    const int wm = wid >> 1, wn = wid & 1;
    const int barid = 1 + wm;
    const int qt = gridDim.x - 1 - blockIdx.x;
    const int bh = blockIdx.y;
    const int q0 = qt * 128;
    const float slope = __ldg(alibi + (size_t)bh * SEQ + 1);  // alibi[k]=slope*k

    // Q plain copy (pre-scaled fp16)
    {
        const int r = tid >> 1, c = (tid & 1) * 64;
        const __half* p = g_qh + ((size_t)bh * SEQ + q0) * HD + (size_t)r * HD + c;
        char* d = Qh + r * STR + c * 2;
        #pragma unroll
        for (int i = 0; i < 8; i++)
            *(uint4*)(d + i * 16) = *(const uint4*)(p + i * 8);
    }

    const __half* kgl = g_kh + (size_t)bh * SEQ * HD;
    const __half* vgl = g_vh + (size_t)bh * SEQ * HD;
    const int lr = tid >> 1, lc = (tid & 1) * 64;
    const uint32_t kdst0 = smem_u32(sm) + 2 * PLN + lr * STR + lc * 2;

    auto issueKV = [&](int kt, int buf) {
        const __half* kp = kgl + (size_t)(kt * 128 + lr) * HD + lc;
        const __half* vp = vgl + (size_t)(kt * 128 + lr) * HD + lc;
        const uint32_t kd = kdst0 + buf * 2 * PLN;
        #pragma unroll
        for (int i = 0; i < 8; i++) {
            cpa16(kd + i * 16, kp + i * 8);
            cpa16(kd + PLN + i * 16, vp + i * 8);
        }
        CP_COMMIT();
    };

    const uint32_t a_off = (uint32_t)(wm * 32 + (lane & 15)) * STR + ((lane >> 4) << 4);
    const uint32_t b_off = (uint32_t)(wn * 64 + (lane & 7) + ((lane >> 4) << 3)) * STR
                         + (((lane >> 3) & 1) << 4);
    // trans-V fragment base: lane -> key (lane&15), d-block (lane>>4)*8
    const uint32_t vt_off = (uint32_t)(lane & 15) * STR
                          + (wn * 64 + ((lane >> 4) << 3)) * 2;
    const uint32_t qh_b = smem_u32(Qh) + a_off;
    const uint32_t ph_b = smem_u32(Pp) + a_off;

    float o[2][8][4];
    float m_[2][2], l_[2][2], corr[2][2];
    #pragma unroll
    for (int mi = 0; mi < 2; mi++)
        #pragma unroll
        for (int rr = 0; rr < 2; rr++) { m_[mi][rr] = -1e30f; l_[mi][rr] = 0.f; }
    #pragma unroll
    for (int mi = 0; mi < 2; mi++)
        #pragma unroll
        for (int nj = 0; nj < 8; nj++)
            #pragma unroll
            for (int r = 0; r < 4; r++) o[mi][nj][r] = 0.f;

    const int rbase = wm * 32 + (lane >> 2);
    const int cq = (lane & 3) * 2;

    issueKV(0, 0);

    for (int kt = 0; kt <= qt; kt++) {
        const int cur = kt & 1;
        if (kt < qt) { issueKV(kt + 1, cur ^ 1); CP_WAIT(1); }
        else         { CP_WAIT(0); }
        __syncthreads();

        const uint32_t kh_b = smem_u32(sm) + (2 + 2 * cur) * PLN + b_off;
        const uint32_t vt_b = smem_u32(sm) + (3 + 2 * cur) * PLN + vt_off;
        const int k0 = kt * 128;

        // ---- S = Q K^T ----
        float s[2][8][4];
        #pragma unroll
        for (int mi = 0; mi < 2; mi++)
            #pragma unroll
            for (int nj = 0; nj < 8; nj++)
                #pragma unroll
                for (int r = 0; r < 4; r++) s[mi][nj][r] = 0.f;
        #pragma unroll
        for (int kk = 0; kk < 8; kk++) {
            uint32_t aH[2][4], bF[4][4];
            ldsm4(aH[0], qh_b + kk * 32);
            ldsm4(aH[1], qh_b + kk * 32 + 16 * STR);
            #pragma unroll
            for (int j2 = 0; j2 < 4; j2++) ldsm4(bF[j2], kh_b + kk * 32 + j2 * 16 * STR);
            #pragma unroll
            for (int mi = 0; mi < 2; mi++)
                #pragma unroll
                for (int j2 = 0; j2 < 4; j2++) {
                    mma16816(s[mi][2*j2],   aH[mi], &bF[j2][0]);
                    mma16816(s[mi][2*j2+1], aH[mi], &bF[j2][2]);
                }
        }

        // ---- alibi (slope*k) + causal + partial row max ----
        const float colf = (float)(k0 + wn * 64 + cq);
        const bool diag = (kt == qt);
        #pragma unroll
        for (int mi = 0; mi < 2; mi++) {
            #pragma unroll
            for (int rr = 0; rr < 2; rr++) {
                const int rloc = rbase + mi * 16 + rr * 8;
                const int rowg = q0 + rloc;
                float mx = -1e30f;
                #pragma unroll
                for (int nj = 0; nj < 8; nj++) {
                    #pragma unroll
                    for (int e = 0; e < 2; e++) {
                        float v = fmaf(slope, colf + (float)(nj * 8 + e), s[mi][nj][rr*2+e]);
                        if (diag && (k0 + wn*64 + nj*8 + cq + e) > rowg) v = -1e30f;
                        s[mi][nj][rr*2+e] = v;
                        mx = fmaxf(mx, v);
                    }
                }
                mx = fmaxf(mx, __shfl_xor_sync(0xffffffffu, mx, 1));
                mx = fmaxf(mx, __shfl_xor_sync(0xffffffffu, mx, 2));
                if ((lane & 3) == 0) red_mx[wn][rloc] = mx;
            }
        }
        BARP(barid);

        // ---- softmax (pair-local) ----
        #pragma unroll
        for (int mi = 0; mi < 2; mi++) {
            #pragma unroll
            for (int rr = 0; rr < 2; rr++) {
                const int rloc = rbase + mi * 16 + rr * 8;
                const float mx = fmaxf(red_mx[0][rloc], red_mx[1][rloc]);
                const float mnew = fmaxf(m_[mi][rr], mx);
                const float cr = __expf(m_[mi][rr] - mnew);
                corr[mi][rr] = cr;
                m_[mi][rr] = mnew;
                float ls = 0.f;
                #pragma unroll
                for (int nj = 0; nj < 8; nj++) {
                    #pragma unroll
                    for (int e = 0; e < 2; e++) {
                        float p = __expf(s[mi][nj][rr*2+e] - mnew);
                        s[mi][nj][rr*2+e] = p;
                        ls += p;
                    }
                }
                ls += __shfl_xor_sync(0xffffffffu, ls, 1);
                ls += __shfl_xor_sync(0xffffffffu, ls, 2);
                if ((lane & 3) == 0) red_sm[wn][rloc] = ls;
                #pragma unroll
                for (int nj = 0; nj < 8; nj++) {
                    o[mi][nj][rr*2]   *= cr;
                    o[mi][nj][rr*2+1] *= cr;
                }
                const uint32_t roff = (uint32_t)rloc * STR + (wn * 64 + cq) * 2;
                #pragma unroll
                for (int nj = 0; nj < 8; nj++)
                    *(uint32_t*)(Pp + roff + nj * 16) =
                        pack_h(s[mi][nj][rr*2], s[mi][nj][rr*2+1]);
            }
        }
        BARP(barid);
        #pragma unroll
        for (int mi = 0; mi < 2; mi++)
            #pragma unroll
            for (int rr = 0; rr < 2; rr++) {
                const int rloc = rbase + mi * 16 + rr * 8;
                l_[mi][rr] = l_[mi][rr] * corr[mi][rr] + red_sm[0][rloc] + red_sm[1][rloc];
            }

        // ---- O += P V  (V via trans-ldsm, no transposed global) ----
        #pragma unroll
        for (int kk = 0; kk < 8; kk++) {
            uint32_t aP[2][4], bT[4][4];
            ldsm4(aP[0], ph_b + kk * 32);
            ldsm4(aP[1], ph_b + kk * 32 + 16 * STR);
            #pragma unroll
            for (int jp = 0; jp < 4; jp++)
                ldsm4t(bT[jp], vt_b + kk * 16 * STR + jp * 32);
            #pragma unroll
            for (int mi = 0; mi < 2; mi++)
                #pragma unroll
                for (int jp = 0; jp < 4; jp++) {
                    mma16816(o[mi][2*jp],   aP[mi], &bT[jp][0]);
                    mma16816(o[mi][2*jp+1], aP[mi], &bT[jp][2]);
                }
        }
        __syncthreads();
    }

    // ---- epilogue -> fp16 ctx ----
    const int b = bh >> 5, h = bh & 31;
    #pragma unroll
    for (int mi = 0; mi < 2; mi++) {
        #pragma unroll
        for (int rr = 0; rr < 2; rr++) {
            const float invl = 1.f / l_[mi][rr];
            const int srow = q0 + rbase + mi * 16 + rr * 8;
            __half* op = g_ctxh + ((size_t)(b * SEQ + srow)) * HID + h * HD
                       + wn * 64 + cq;
            #pragma unroll
            for (int nj = 0; nj < 8; nj++)
                *(uint32_t*)(op + nj * 8) = pack_h(o[mi][nj][rr*2] * invl,
                                                   o[mi][nj][rr*2+1] * invl);
        }
    }
}

// =============================== launch ====================================
extern "C" void kernel_launch(void* const* d_in, const int* in_sizes, int n_in,
                              void* d_out, int out_size)
{
    const float* hs    = (const float*)d_in[0];
    const float* resid = (const float*)d_in[1];
    const float* alibi = (const float*)d_in[2];
    const float* Wqkv  = (const float*)d_in[4];
    const float* bqkv  = (const float*)d_in[5];
    const float* Wd    = (const float*)d_in[6];
    const float* bd    = (const float*)d_in[7];
    float* out = (float*)d_out;

    cudaFuncSetAttribute(gemm_mma_kernel<true>,
                         cudaFuncAttributeMaxDynamicSharedMemorySize, GEMM_SMEM);
    cudaFuncSetAttribute(gemm_mma_kernel<false>,
                         cudaFuncAttributeMaxDynamicSharedMemorySize, GEMM_SMEM);
    cudaFuncSetAttribute(attn_mma_kernel,
                         cudaFuncAttributeMaxDynamicSharedMemorySize, ATT_SMEM);

    __half* d_ah;    cudaGetSymbolAddress((void**)&d_ah,    g_ah);
    __half* d_wqkvT; cudaGetSymbolAddress((void**)&d_wqkvT, g_wqkvT);
    __half* d_wdT;   cudaGetSymbolAddress((void**)&d_wdT,   g_wdT);
    __half* d_ctxh;  cudaGetSymbolAddress((void**)&d_ctxh,  g_ctxh);

    conv_fp16_kernel<<<(MROWS * HID / 4 + 255) / 256, 256>>>(hs, d_ah, MROWS * HID / 4);
    transpose_fp16_kernel<<<dim3(NQKV / 32, HID / 32), dim3(32, 8)>>>(Wqkv, d_wqkvT, HID, NQKV);
    transpose_fp16_kernel<<<dim3(HID / 32, HID / 32), dim3(32, 8)>>>(Wd, d_wdT, HID, HID);

    gemm_mma_kernel<true><<<dim3(NQKV/128, MROWS/256), 512, GEMM_SMEM>>>(d_ah, d_wqkvT, bqkv, nullptr, nullptr);
    attn_mma_kernel<<<dim3(SEQ/128, BATCH*NH), 256, ATT_SMEM>>>(alibi);
    gemm_mma_kernel<false><<<dim3(HID/128, MROWS/256), 512, GEMM_SMEM>>>(d_ctxh, d_wdT, bd, resid, out);
}

// round 15
// speedup vs baseline: 1.6976x; 1.0195x over previous
#include <cuda_runtime.h>
#include <cuda_fp16.h>
#include <stdint.h>

#define HID   4096
#define SEQ   2048
#define BATCH 2
#define NH    32
#define HD    128
#define MROWS (BATCH*SEQ)
#define NQKV  (3*HID)

__device__ __half g_ah  [(size_t)MROWS*HID];
__device__ __half g_wqkvT[(size_t)NQKV*HID];
__device__ __half g_wdT [(size_t)HID*HID];
__device__ __half g_qh  [(size_t)BATCH*NH*SEQ*HD];   // pre-scaled
__device__ __half g_kh  [(size_t)BATCH*NH*SEQ*HD];
__device__ __half g_vh  [(size_t)BATCH*NH*SEQ*HD];   // [bh][s][d]
__device__ __half g_ctxh[(size_t)MROWS*HID];

// ============================ helpers ======================================
__device__ __forceinline__ uint32_t smem_u32(const void* p) {
    uint32_t a;
    asm("{ .reg .u64 t; cvta.to.shared.u64 t, %1; cvt.u32.u64 %0, t; }" : "=r"(a) : "l"(p));
    return a;
}
__device__ __forceinline__ void ldsm4(uint32_t* r, uint32_t addr) {
    asm volatile("ldmatrix.sync.aligned.m8n8.x4.shared.b16 {%0,%1,%2,%3}, [%4];"
                 : "=r"(r[0]), "=r"(r[1]), "=r"(r[2]), "=r"(r[3]) : "r"(addr));
}
__device__ __forceinline__ void ldsm4t(uint32_t* r, uint32_t addr) {
    asm volatile("ldmatrix.sync.aligned.m8n8.x4.trans.shared.b16 {%0,%1,%2,%3}, [%4];"
                 : "=r"(r[0]), "=r"(r[1]), "=r"(r[2]), "=r"(r[3]) : "r"(addr));
}
__device__ __forceinline__ void mma16816(float* d, const uint32_t* a, const uint32_t* b) {
    asm volatile("mma.sync.aligned.m16n8k16.row.col.f32.f16.f16.f32 "
                 "{%0,%1,%2,%3}, {%4,%5,%6,%7}, {%8,%9}, {%0,%1,%2,%3};"
                 : "+f"(d[0]), "+f"(d[1]), "+f"(d[2]), "+f"(d[3])
                 : "r"(a[0]), "r"(a[1]), "r"(a[2]), "r"(a[3]), "r"(b[0]), "r"(b[1]));
}
__device__ __forceinline__ uint32_t pack_h(float a, float b) {
    __half2 hh = __floats2half2_rn(a, b);
    return *(uint32_t*)&hh;
}
__device__ __forceinline__ void cpa16(uint32_t dst, const void* src) {
    asm volatile("cp.async.cg.shared.global [%0], [%1], 16;" :: "r"(dst), "l"(src));
}
#define CP_COMMIT() asm volatile("cp.async.commit_group;" ::: "memory")
#define CP_WAIT(n)  asm volatile("cp.async.wait_group %0;" :: "n"(n) : "memory")
#define BARG(id)    asm volatile("bar.sync %0, 128;" :: "r"(id) : "memory")

// ===================== conversion prologue kernels =========================
__global__ void conv_fp16_kernel(const float* __restrict__ src,
                                 __half* __restrict__ dst, int n4)
{
    const int i = blockIdx.x * blockDim.x + threadIdx.x;
    if (i < n4) {
        float4 v = ((const float4*)src)[i];
        uint2 o;
        o.x = pack_h(v.x, v.y);
        o.y = pack_h(v.z, v.w);
        ((uint2*)dst)[i] = o;
    }
}
__global__ void transpose_fp16_kernel(const float* __restrict__ src,
                                      __half* __restrict__ dst, int R, int C)
{
    __shared__ float t[32][33];
    const int x = blockIdx.x * 32 + threadIdx.x;
    const int y0 = blockIdx.y * 32;
    #pragma unroll
    for (int j = 0; j < 4; j++)
        t[threadIdx.y + j * 8][threadIdx.x] = src[(size_t)(y0 + threadIdx.y + j * 8) * C + x];
    __syncthreads();
    const int xo = y0 + threadIdx.x;
    const int yo0 = blockIdx.x * 32;
    #pragma unroll
    for (int j = 0; j < 4; j++)
        dst[(size_t)(yo0 + threadIdx.y + j * 8) * R + xo] =
            __float2half(t[threadIdx.x][threadIdx.y + j * 8]);
}

// == fp16 GEMM: CTA 256x128, 16 warps (4x4), warp 64x32, KCH=64, 4-stage ====
#define KCH    64
#define ROWB   144
#define APLANE (256*ROWB)
#define BPLANE (128*ROWB)
#define STAGE  (APLANE+BPLANE)
#define NSTG   4
#define GEMM_SMEM (NSTG*STAGE)

template <bool IS_QKV>
__global__ void __launch_bounds__(512, 1)
gemm_mma_kernel(const __half* __restrict__ Ah, const __half* __restrict__ Wt,
                const float* __restrict__ bias, const float* __restrict__ resid,
                float* __restrict__ out)
{
    constexpr int NC = HID / KCH;
    extern __shared__ __align__(16) char stg[];
    const uint32_t stg_u = smem_u32(stg);

    const int tid = threadIdx.x;
    const int wid = tid >> 5, lane = tid & 31;
    const int wm  = wid >> 2, wn = wid & 3;
    const int m0  = blockIdx.y * 256, n0 = blockIdx.x * 128;

    const int lrow = tid >> 3, lseg = tid & 7;
    const __half* aS = Ah + (size_t)(m0 + lrow) * HID + lseg * 8;
    const __half* bS = Wt + (size_t)(n0 + lrow) * HID + lseg * 8;
    const uint32_t aD = stg_u + lrow * ROWB + lseg * 16;
    const uint32_t bD = stg_u + APLANE + lrow * ROWB + lseg * 16;

    auto issue = [&](int c) {
        const uint32_t off = (uint32_t)(c % NSTG) * STAGE;
        const size_t k0 = (size_t)c * KCH;
        #pragma unroll
        for (int i = 0; i < 4; i++)
            cpa16(aD + off + i * 64 * ROWB, aS + k0 + (size_t)i * 64 * HID);
        #pragma unroll
        for (int i = 0; i < 2; i++)
            cpa16(bD + off + i * 64 * ROWB, bS + k0 + (size_t)i * 64 * HID);
        CP_COMMIT();
    };

    float acc[4][4][4];
    #pragma unroll
    for (int mi = 0; mi < 4; mi++)
        #pragma unroll
        for (int nj = 0; nj < 4; nj++)
            #pragma unroll
            for (int r = 0; r < 4; r++) acc[mi][nj][r] = 0.f;

    const uint32_t a_base = stg_u + (uint32_t)(wm * 64 + (lane & 15)) * ROWB + ((lane >> 4) << 4);
    const uint32_t b_base = stg_u + APLANE
                          + (uint32_t)(wn * 32 + (lane & 7) + ((lane >> 4) << 3)) * ROWB
                          + (((lane >> 3) & 1) << 4);

    issue(0); issue(1); issue(2);

    for (int c = 0; c < NC; c++) {
        CP_WAIT(2);
        __syncthreads();

        const uint32_t soff = (uint32_t)(c % NSTG) * STAGE;
        const uint32_t ab = a_base + soff;
        const uint32_t bb = b_base + soff;
        #pragma unroll
        for (int kk = 0; kk < 4; kk++) {
            uint32_t aH[4][4], bF[2][4];
            #pragma unroll
            for (int mi = 0; mi < 4; mi++) ldsm4(aH[mi], ab + kk * 32 + mi * 16 * ROWB);
            #pragma unroll
            for (int j2 = 0; j2 < 2; j2++) ldsm4(bF[j2], bb + kk * 32 + j2 * 16 * ROWB);
            #pragma unroll
            for (int mi = 0; mi < 4; mi++)
                #pragma unroll
                for (int j2 = 0; j2 < 2; j2++) {
                    mma16816(acc[mi][2*j2],   aH[mi], &bF[j2][0]);
                    mma16816(acc[mi][2*j2+1], aH[mi], &bF[j2][2]);
                }
        }

        if (c + 3 < NC) issue(c + 3);
        else            CP_COMMIT();
    }

    // epilogue
    const float inv_norm = 0.088388347648318447f;
    float b2x[4], b2y[4];
    #pragma unroll
    for (int nj = 0; nj < 4; nj++) {
        const int col = n0 + wn * 32 + nj * 8 + (lane & 3) * 2;
        b2x[nj] = __ldg(&bias[col]);
        b2y[nj] = __ldg(&bias[col + 1]);
    }
    if (IS_QKV) {
        const int h = blockIdx.x / 3, comp = blockIdx.x % 3;
        __half* gbase = (comp == 0) ? g_qh : (comp == 1) ? g_kh : g_vh;
        const float scl = (comp == 0) ? inv_norm : 1.f;
        #pragma unroll
        for (int mi = 0; mi < 4; mi++) {
            #pragma unroll
            for (int rr = 0; rr < 2; rr++) {
                const int row = m0 + wm * 64 + mi * 16 + (lane >> 2) + rr * 8;
                const int bbat = row >> 11, ss = row & 2047;
                __half* dstrow = gbase + ((size_t)(bbat * NH + h) * SEQ + ss) * HD;
                #pragma unroll
                for (int nj = 0; nj < 4; nj++) {
                    const int d = wn * 32 + nj * 8 + (lane & 3) * 2;
                    float vx = (acc[mi][nj][rr*2]   + b2x[nj]) * scl;
                    float vy = (acc[mi][nj][rr*2+1] + b2y[nj]) * scl;
                    *(uint32_t*)(dstrow + d) = pack_h(vx, vy);
                }
            }
        }
    } else {
        #pragma unroll
        for (int mi = 0; mi < 4; mi++) {
            #pragma unroll
            for (int rr = 0; rr < 2; rr++) {
                const int row = m0 + wm * 64 + mi * 16 + (lane >> 2) + rr * 8;
                const size_t o = (size_t)row * HID + n0 + wn * 32 + (lane & 3) * 2;
                #pragma unroll
                for (int nj = 0; nj < 4; nj++) {
                    float2 rv = *(const float2*)(resid + o + nj * 8);
                    *(float2*)(out + o + nj * 8) =
                        make_float2(acc[mi][nj][rr*2] + b2x[nj] + rv.x,
                                    acc[mi][nj][rr*2+1] + b2y[nj] + rv.y);
                }
            }
        }
    }
}

// ==== flash attention: 512 thr, 4x4 warp grid, warp-group softmax =========
// planes (stride 272B, 128 rows): Q | P | K0 | V0 | K1 | V1
#define STR  272
#define PLN  (128*STR)
#define ATT_SMEM (6*PLN)

__global__ void __launch_bounds__(512, 1) attn_mma_kernel(const float* __restrict__ alibi)
{
    extern __shared__ __align__(16) char sm[];
    char* Qh = sm;
    char* Pp = sm + PLN;
    __shared__ float red_mx[4][128];
    __shared__ float red_sm[4][128];

    const int tid = threadIdx.x;
    const int wid = tid >> 5, lane = tid & 31;
    const int wm = wid >> 2, wn = wid & 3;    // 4x4: 32-row group x 32-col group
    const int barid = 1 + wm;                 // 128-thread row-group barrier
    const int qt = gridDim.x - 1 - blockIdx.x;
    const int bh = blockIdx.y;
    const int q0 = qt * 128;
    const float slope = __ldg(alibi + (size_t)bh * SEQ + 1);  // alibi[k]=slope*k

    // Q copy: 512 threads, 64B each
    {
        const int r = tid >> 2, c = (tid & 3) * 32;
        const __half* p = g_qh + ((size_t)bh * SEQ + q0) * HD + (size_t)r * HD + c;
        char* d = Qh + r * STR + c * 2;
        #pragma unroll
        for (int i = 0; i < 4; i++)
            *(uint4*)(d + i * 16) = *(const uint4*)(p + i * 8);
    }

    const __half* kgl = g_kh + (size_t)bh * SEQ * HD;
    const __half* vgl = g_vh + (size_t)bh * SEQ * HD;
    const int lr = tid >> 2, lc = (tid & 3) * 32;
    const uint32_t kdst0 = smem_u32(sm) + 2 * PLN + lr * STR + lc * 2;

    auto issueKV = [&](int kt, int buf) {
        const __half* kp = kgl + (size_t)(kt * 128 + lr) * HD + lc;
        const __half* vp = vgl + (size_t)(kt * 128 + lr) * HD + lc;
        const uint32_t kd = kdst0 + buf * 2 * PLN;
        #pragma unroll
        for (int i = 0; i < 4; i++) {
            cpa16(kd + i * 16, kp + i * 8);
            cpa16(kd + PLN + i * 16, vp + i * 8);
        }
        CP_COMMIT();
    };

    const uint32_t a_off = (uint32_t)(wm * 32 + (lane & 15)) * STR + ((lane >> 4) << 4);
    const uint32_t b_off = (uint32_t)(wn * 32 + (lane & 7) + ((lane >> 4) << 3)) * STR
                         + (((lane >> 3) & 1) << 4);
    const uint32_t vt_off = (uint32_t)(lane & 15) * STR
                          + (wn * 32 + ((lane >> 4) << 3)) * 2;
    const uint32_t qh_b = smem_u32(Qh) + a_off;
    const uint32_t ph_b = smem_u32(Pp) + a_off;

    float o[2][4][4];
    float m_[2][2], l_[2][2], corr[2][2];
    #pragma unroll
    for (int mi = 0; mi < 2; mi++)
        #pragma unroll
        for (int rr = 0; rr < 2; rr++) { m_[mi][rr] = -1e30f; l_[mi][rr] = 0.f; }
    #pragma unroll
    for (int mi = 0; mi < 2; mi++)
        #pragma unroll
        for (int nj = 0; nj < 4; nj++)
            #pragma unroll
            for (int r = 0; r < 4; r++) o[mi][nj][r] = 0.f;

    const int rbase = wm * 32 + (lane >> 2);
    const int cq = (lane & 3) * 2;

    issueKV(0, 0);

    for (int kt = 0; kt <= qt; kt++) {
        const int cur = kt & 1;
        if (kt < qt) { issueKV(kt + 1, cur ^ 1); CP_WAIT(1); }
        else         { CP_WAIT(0); }
        __syncthreads();

        const uint32_t kh_b = smem_u32(sm) + (2 + 2 * cur) * PLN + b_off;
        const uint32_t vt_b = smem_u32(sm) + (3 + 2 * cur) * PLN + vt_off;
        const int k0 = kt * 128;

        // ---- S = Q K^T (warp: 32 rows x 32 K-cols) ----
        float s[2][4][4];
        #pragma unroll
        for (int mi = 0; mi < 2; mi++)
            #pragma unroll
            for (int nj = 0; nj < 4; nj++)
                #pragma unroll
                for (int r = 0; r < 4; r++) s[mi][nj][r] = 0.f;
        #pragma unroll
        for (int kk = 0; kk < 8; kk++) {
            uint32_t aH[2][4], bF[2][4];
            ldsm4(aH[0], qh_b + kk * 32);
            ldsm4(aH[1], qh_b + kk * 32 + 16 * STR);
            #pragma unroll
            for (int j2 = 0; j2 < 2; j2++) ldsm4(bF[j2], kh_b + kk * 32 + j2 * 16 * STR);
            #pragma unroll
            for (int mi = 0; mi < 2; mi++)
                #pragma unroll
                for (int j2 = 0; j2 < 2; j2++) {
                    mma16816(s[mi][2*j2],   aH[mi], &bF[j2][0]);
                    mma16816(s[mi][2*j2+1], aH[mi], &bF[j2][2]);
                }
        }

        // ---- alibi (slope*k) + causal + partial row max ----
        const float colf = (float)(k0 + wn * 32 + cq);
        const bool diag = (kt == qt);
        #pragma unroll
        for (int mi = 0; mi < 2; mi++) {
            #pragma unroll
            for (int rr = 0; rr < 2; rr++) {
                const int rloc = rbase + mi * 16 + rr * 8;
                const int rowg = q0 + rloc;
                float mx = -1e30f;
                #pragma unroll
                for (int nj = 0; nj < 4; nj++) {
                    #pragma unroll
                    for (int e = 0; e < 2; e++) {
                        float v = fmaf(slope, colf + (float)(nj * 8 + e), s[mi][nj][rr*2+e]);
                        if (diag && (k0 + wn*32 + nj*8 + cq + e) > rowg) v = -1e30f;
                        s[mi][nj][rr*2+e] = v;
                        mx = fmaxf(mx, v);
                    }
                }
                mx = fmaxf(mx, __shfl_xor_sync(0xffffffffu, mx, 1));
                mx = fmaxf(mx, __shfl_xor_sync(0xffffffffu, mx, 2));
                if ((lane & 3) == 0) red_mx[wn][rloc] = mx;
            }
        }
        BARG(barid);                          // row group: maxes exchanged

        // ---- softmax (group-local) ----
        #pragma unroll
        for (int mi = 0; mi < 2; mi++) {
            #pragma unroll
            for (int rr = 0; rr < 2; rr++) {
                const int rloc = rbase + mi * 16 + rr * 8;
                const float mx = fmaxf(fmaxf(red_mx[0][rloc], red_mx[1][rloc]),
                                       fmaxf(red_mx[2][rloc], red_mx[3][rloc]));
                const float mnew = fmaxf(m_[mi][rr], mx);
                const float cr = __expf(m_[mi][rr] - mnew);
                corr[mi][rr] = cr;
                m_[mi][rr] = mnew;
                float ls = 0.f;
                #pragma unroll
                for (int nj = 0; nj < 4; nj++) {
                    #pragma unroll
                    for (int e = 0; e < 2; e++) {
                        float p = __expf(s[mi][nj][rr*2+e] - mnew);
                        s[mi][nj][rr*2+e] = p;
                        ls += p;
                    }
                }
                ls += __shfl_xor_sync(0xffffffffu, ls, 1);
                ls += __shfl_xor_sync(0xffffffffu, ls, 2);
                if ((lane & 3) == 0) red_sm[wn][rloc] = ls;
                #pragma unroll
                for (int nj = 0; nj < 4; nj++) {
                    o[mi][nj][rr*2]   *= cr;
                    o[mi][nj][rr*2+1] *= cr;
                }
                // write P block (32 cols per warp)
                const uint32_t roff = (uint32_t)rloc * STR + (wn * 32 + cq) * 2;
                #pragma unroll
                for (int nj = 0; nj < 4; nj++)
                    *(uint32_t*)(Pp + roff + nj * 16) =
                        pack_h(s[mi][nj][rr*2], s[mi][nj][rr*2+1]);
            }
        }
        BARG(barid);                          // sums + P rows ready
        #pragma unroll
        for (int mi = 0; mi < 2; mi++)
            #pragma unroll
            for (int rr = 0; rr < 2; rr++) {
                const int rloc = rbase + mi * 16 + rr * 8;
                l_[mi][rr] = l_[mi][rr] * corr[mi][rr]
                           + red_sm[0][rloc] + red_sm[1][rloc]
                           + red_sm[2][rloc] + red_sm[3][rloc];
            }

        // ---- O += P V  (A: P rows over full 128 k; B: trans-ldsm V 32 d) --
        #pragma unroll
        for (int kk = 0; kk < 8; kk++) {
            uint32_t aP[2][4], bT[2][4];
            ldsm4(aP[0], ph_b + kk * 32);
            ldsm4(aP[1], ph_b + kk * 32 + 16 * STR);
            #pragma unroll
            for (int jp = 0; jp < 2; jp++)
                ldsm4t(bT[jp], vt_b + kk * 16 * STR + jp * 32);
            #pragma unroll
            for (int mi = 0; mi < 2; mi++)
                #pragma unroll
                for (int jp = 0; jp < 2; jp++) {
                    mma16816(o[mi][2*jp],   aP[mi], &bT[jp][0]);
                    mma16816(o[mi][2*jp+1], aP[mi], &bT[jp][2]);
                }
        }
        __syncthreads();                      // K/V cur free for reissue
    }

    // ---- epilogue -> fp16 ctx ----
    const int b = bh >> 5, h = bh & 31;
    #pragma unroll
    for (int mi = 0; mi < 2; mi++) {
        #pragma unroll
        for (int rr = 0; rr < 2; rr++) {
            const float invl = 1.f / l_[mi][rr];
            const int srow = q0 + rbase + mi * 16 + rr * 8;
            __half* op = g_ctxh + ((size_t)(b * SEQ + srow)) * HID + h * HD
                       + wn * 32 + cq;
            #pragma unroll
            for (int nj = 0; nj < 4; nj++)
                *(uint32_t*)(op + nj * 8) = pack_h(o[mi][nj][rr*2] * invl,
                                                   o[mi][nj][rr*2+1] * invl);
        }
    }
}

// =============================== launch ====================================
extern "C" void kernel_launch(void* const* d_in, const int* in_sizes, int n_in,
                              void* d_out, int out_size)
{
    const float* hs    = (const float*)d_in[0];
    const float* resid = (const float*)d_in[1];
    const float* alibi = (const float*)d_in[2];
    const float* Wqkv  = (const float*)d_in[4];
    const float* bqkv  = (const float*)d_in[5];
    const float* Wd    = (const float*)d_in[6];
    const float* bd    = (const float*)d_in[7];
    float* out = (float*)d_out;

    cudaFuncSetAttribute(gemm_mma_kernel<true>,
                         cudaFuncAttributeMaxDynamicSharedMemorySize, GEMM_SMEM);
    cudaFuncSetAttribute(gemm_mma_kernel<false>,
                         cudaFuncAttributeMaxDynamicSharedMemorySize, GEMM_SMEM);
    cudaFuncSetAttribute(attn_mma_kernel,
                         cudaFuncAttributeMaxDynamicSharedMemorySize, ATT_SMEM);

    __half* d_ah;    cudaGetSymbolAddress((void**)&d_ah,    g_ah);
    __half* d_wqkvT; cudaGetSymbolAddress((void**)&d_wqkvT, g_wqkvT);
    __half* d_wdT;   cudaGetSymbolAddress((void**)&d_wdT,   g_wdT);
    __half* d_ctxh;  cudaGetSymbolAddress((void**)&d_ctxh,  g_ctxh);

    conv_fp16_kernel<<<(MROWS * HID / 4 + 255) / 256, 256>>>(hs, d_ah, MROWS * HID / 4);
    transpose_fp16_kernel<<<dim3(NQKV / 32, HID / 32), dim3(32, 8)>>>(Wqkv, d_wqkvT, HID, NQKV);
    transpose_fp16_kernel<<<dim3(HID / 32, HID / 32), dim3(32, 8)>>>(Wd, d_wdT, HID, HID);

    gemm_mma_kernel<true><<<dim3(NQKV/128, MROWS/256), 512, GEMM_SMEM>>>(d_ah, d_wqkvT, bqkv, nullptr, nullptr);
    attn_mma_kernel<<<dim3(SEQ/128, BATCH*NH), 512, ATT_SMEM>>>(alibi);
    gemm_mma_kernel<false><<<dim3(HID/128, MROWS/256), 512, GEMM_SMEM>>>(d_ctxh, d_wdT, bd, resid, out);
}

// round 16
// speedup vs baseline: 1.7088x; 1.0066x over previous
#include <cuda_runtime.h>
#include <cuda_fp16.h>
#include <stdint.h>

#define HID   4096
#define SEQ   2048
#define BATCH 2
#define NH    32
#define HD    128
#define MROWS (BATCH*SEQ)
#define NQKV  (3*HID)

__device__ __half g_ah  [(size_t)MROWS*HID];
__device__ __half g_wqkvT[(size_t)NQKV*HID];
__device__ __half g_wdT [(size_t)HID*HID];
__device__ __half g_qh  [(size_t)BATCH*NH*SEQ*HD];   // pre-scaled
__device__ __half g_kh  [(size_t)BATCH*NH*SEQ*HD];
__device__ __half g_vh  [(size_t)BATCH*NH*SEQ*HD];   // [bh][s][d]
__device__ __half g_ctxh[(size_t)MROWS*HID];

// ============================ helpers ======================================
__device__ __forceinline__ uint32_t smem_u32(const void* p) {
    uint32_t a;
    asm("{ .reg .u64 t; cvta.to.shared.u64 t, %1; cvt.u32.u64 %0, t; }" : "=r"(a) : "l"(p));
    return a;
}
__device__ __forceinline__ void ldsm4(uint32_t* r, uint32_t addr) {
    asm volatile("ldmatrix.sync.aligned.m8n8.x4.shared.b16 {%0,%1,%2,%3}, [%4];"
                 : "=r"(r[0]), "=r"(r[1]), "=r"(r[2]), "=r"(r[3]) : "r"(addr));
}
__device__ __forceinline__ void ldsm4t(uint32_t* r, uint32_t addr) {
    asm volatile("ldmatrix.sync.aligned.m8n8.x4.trans.shared.b16 {%0,%1,%2,%3}, [%4];"
                 : "=r"(r[0]), "=r"(r[1]), "=r"(r[2]), "=r"(r[3]) : "r"(addr));
}
__device__ __forceinline__ void mma16816(float* d, const uint32_t* a, const uint32_t* b) {
    asm volatile("mma.sync.aligned.m16n8k16.row.col.f32.f16.f16.f32 "
                 "{%0,%1,%2,%3}, {%4,%5,%6,%7}, {%8,%9}, {%0,%1,%2,%3};"
                 : "+f"(d[0]), "+f"(d[1]), "+f"(d[2]), "+f"(d[3])
                 : "r"(a[0]), "r"(a[1]), "r"(a[2]), "r"(a[3]), "r"(b[0]), "r"(b[1]));
}
__device__ __forceinline__ uint32_t pack_h(float a, float b) {
    __half2 hh = __floats2half2_rn(a, b);
    return *(uint32_t*)&hh;
}
__device__ __forceinline__ void cpa16(uint32_t dst, const void* src) {
    asm volatile("cp.async.cg.shared.global [%0], [%1], 16;" :: "r"(dst), "l"(src));
}
#define CP_COMMIT() asm volatile("cp.async.commit_group;" ::: "memory")
#define CP_WAIT(n)  asm volatile("cp.async.wait_group %0;" :: "n"(n) : "memory")
#define BARG(id)    asm volatile("bar.sync %0, 128;" :: "r"(id) : "memory")

// ===================== conversion prologue kernels =========================
__global__ void conv_fp16_kernel(const float* __restrict__ src,
                                 __half* __restrict__ dst, int n4)
{
    const int i = blockIdx.x * blockDim.x + threadIdx.x;
    if (i < n4) {
        float4 v = ((const float4*)src)[i];
        uint2 o;
        o.x = pack_h(v.x, v.y);
        o.y = pack_h(v.z, v.w);
        ((uint2*)dst)[i] = o;
    }
}
__global__ void transpose_fp16_kernel(const float* __restrict__ src,
                                      __half* __restrict__ dst, int R, int C)
{
    __shared__ float t[32][33];
    const int x = blockIdx.x * 32 + threadIdx.x;
    const int y0 = blockIdx.y * 32;
    #pragma unroll
    for (int j = 0; j < 4; j++)
        t[threadIdx.y + j * 8][threadIdx.x] = src[(size_t)(y0 + threadIdx.y + j * 8) * C + x];
    __syncthreads();
    const int xo = y0 + threadIdx.x;
    const int yo0 = blockIdx.x * 32;
    #pragma unroll
    for (int j = 0; j < 4; j++)
        dst[(size_t)(yo0 + threadIdx.y + j * 8) * R + xo] =
            __float2half(t[threadIdx.x][threadIdx.y + j * 8]);
}

// == fp16 GEMM: CTA 256x128, 16 warps (4x4), warp 64x32, KCH=64, 4-stage ====
#define KCH    64
#define ROWB   144
#define APLANE (256*ROWB)
#define BPLANE (128*ROWB)
#define STAGE  (APLANE+BPLANE)
#define NSTG   4
#define GEMM_SMEM (NSTG*STAGE)

template <bool IS_QKV>
__global__ void __launch_bounds__(512, 1)
gemm_mma_kernel(const __half* __restrict__ Ah, const __half* __restrict__ Wt,
                const float* __restrict__ bias, const float* __restrict__ resid,
                float* __restrict__ out)
{
    constexpr int NC = HID / KCH;
    extern __shared__ __align__(16) char stg[];
    const uint32_t stg_u = smem_u32(stg);

    const int tid = threadIdx.x;
    const int wid = tid >> 5, lane = tid & 31;
    const int wm  = wid >> 2, wn = wid & 3;
    const int m0  = blockIdx.y * 256, n0 = blockIdx.x * 128;

    const int lrow = tid >> 3, lseg = tid & 7;
    const __half* aS = Ah + (size_t)(m0 + lrow) * HID + lseg * 8;
    const __half* bS = Wt + (size_t)(n0 + lrow) * HID + lseg * 8;
    const uint32_t aD = stg_u + lrow * ROWB + lseg * 16;
    const uint32_t bD = stg_u + APLANE + lrow * ROWB + lseg * 16;

    auto issue = [&](int c) {
        const uint32_t off = (uint32_t)(c % NSTG) * STAGE;
        const size_t k0 = (size_t)c * KCH;
        #pragma unroll
        for (int i = 0; i < 4; i++)
            cpa16(aD + off + i * 64 * ROWB, aS + k0 + (size_t)i * 64 * HID);
        #pragma unroll
        for (int i = 0; i < 2; i++)
            cpa16(bD + off + i * 64 * ROWB, bS + k0 + (size_t)i * 64 * HID);
        CP_COMMIT();
    };

    float acc[4][4][4];
    #pragma unroll
    for (int mi = 0; mi < 4; mi++)
        #pragma unroll
        for (int nj = 0; nj < 4; nj++)
            #pragma unroll
            for (int r = 0; r < 4; r++) acc[mi][nj][r] = 0.f;

    const uint32_t a_base = stg_u + (uint32_t)(wm * 64 + (lane & 15)) * ROWB + ((lane >> 4) << 4);
    const uint32_t b_base = stg_u + APLANE
                          + (uint32_t)(wn * 32 + (lane & 7) + ((lane >> 4) << 3)) * ROWB
                          + (((lane >> 3) & 1) << 4);

    issue(0); issue(1); issue(2);

    for (int c = 0; c < NC; c++) {
        CP_WAIT(2);
        __syncthreads();

        const uint32_t soff = (uint32_t)(c % NSTG) * STAGE;
        const uint32_t ab = a_base + soff;
        const uint32_t bb = b_base + soff;
        #pragma unroll
        for (int kk = 0; kk < 4; kk++) {
            uint32_t aH[4][4], bF[2][4];
            #pragma unroll
            for (int mi = 0; mi < 4; mi++) ldsm4(aH[mi], ab + kk * 32 + mi * 16 * ROWB);
            #pragma unroll
            for (int j2 = 0; j2 < 2; j2++) ldsm4(bF[j2], bb + kk * 32 + j2 * 16 * ROWB);
            #pragma unroll
            for (int mi = 0; mi < 4; mi++)
                #pragma unroll
                for (int j2 = 0; j2 < 2; j2++) {
                    mma16816(acc[mi][2*j2],   aH[mi], &bF[j2][0]);
                    mma16816(acc[mi][2*j2+1], aH[mi], &bF[j2][2]);
                }
        }

        if (c + 3 < NC) issue(c + 3);
        else            CP_COMMIT();
    }

    // epilogue
    const float inv_norm = 0.088388347648318447f;
    float b2x[4], b2y[4];
    #pragma unroll
    for (int nj = 0; nj < 4; nj++) {
        const int col = n0 + wn * 32 + nj * 8 + (lane & 3) * 2;
        b2x[nj] = __ldg(&bias[col]);
        b2y[nj] = __ldg(&bias[col + 1]);
    }
    if (IS_QKV) {
        const int h = blockIdx.x / 3, comp = blockIdx.x % 3;
        __half* gbase = (comp == 0) ? g_qh : (comp == 1) ? g_kh : g_vh;
        const float scl = (comp == 0) ? inv_norm : 1.f;
        #pragma unroll
        for (int mi = 0; mi < 4; mi++) {
            #pragma unroll
            for (int rr = 0; rr < 2; rr++) {
                const int row = m0 + wm * 64 + mi * 16 + (lane >> 2) + rr * 8;
                const int bbat = row >> 11, ss = row & 2047;
                __half* dstrow = gbase + ((size_t)(bbat * NH + h) * SEQ + ss) * HD;
                #pragma unroll
                for (int nj = 0; nj < 4; nj++) {
                    const int d = wn * 32 + nj * 8 + (lane & 3) * 2;
                    float vx = (acc[mi][nj][rr*2]   + b2x[nj]) * scl;
                    float vy = (acc[mi][nj][rr*2+1] + b2y[nj]) * scl;
                    *(uint32_t*)(dstrow + d) = pack_h(vx, vy);
                }
            }
        }
    } else {
        #pragma unroll
        for (int mi = 0; mi < 4; mi++) {
            #pragma unroll
            for (int rr = 0; rr < 2; rr++) {
                const int row = m0 + wm * 64 + mi * 16 + (lane >> 2) + rr * 8;
                const size_t o = (size_t)row * HID + n0 + wn * 32 + (lane & 3) * 2;
                #pragma unroll
                for (int nj = 0; nj < 4; nj++) {
                    float2 rv = *(const float2*)(resid + o + nj * 8);
                    *(float2*)(out + o + nj * 8) =
                        make_float2(acc[mi][nj][rr*2] + b2x[nj] + rv.x,
                                    acc[mi][nj][rr*2+1] + b2y[nj] + rv.y);
                }
            }
        }
    }
}

// ==== flash attention: 512 thr, 4x4 grid, 1 barrier/tile, diag split ======
// planes (stride 272B, 128 rows): Q | P | K0 | V0 | K1 | V1
#define STR  272
#define PLN  (128*STR)
#define ATT_SMEM (6*PLN)

__global__ void __launch_bounds__(512, 1) attn_mma_kernel(const float* __restrict__ alibi)
{
    extern __shared__ __align__(16) char sm[];
    char* Qh = sm;
    char* Pp = sm + PLN;
    __shared__ float red_mx[4][128];
    __shared__ float red_sm[4][128];

    const int tid = threadIdx.x;
    const int wid = tid >> 5, lane = tid & 31;
    const int wm = wid >> 2, wn = wid & 3;
    const int barid = 1 + wm;
    const int qt = gridDim.x - 1 - blockIdx.x;
    const int bh = blockIdx.y;
    const int q0 = qt * 128;
    const float slope = __ldg(alibi + (size_t)bh * SEQ + 1);

    // Q copy
    {
        const int r = tid >> 2, c = (tid & 3) * 32;
        const __half* p = g_qh + ((size_t)bh * SEQ + q0) * HD + (size_t)r * HD + c;
        char* d = Qh + r * STR + c * 2;
        #pragma unroll
        for (int i = 0; i < 4; i++)
            *(uint4*)(d + i * 16) = *(const uint4*)(p + i * 8);
    }

    const __half* kgl = g_kh + (size_t)bh * SEQ * HD;
    const __half* vgl = g_vh + (size_t)bh * SEQ * HD;
    const int lr = tid >> 2, lc = (tid & 3) * 32;
    const uint32_t kdst0 = smem_u32(sm) + 2 * PLN + lr * STR + lc * 2;

    auto issueKV = [&](int kt, int buf) {
        const __half* kp = kgl + (size_t)(kt * 128 + lr) * HD + lc;
        const __half* vp = vgl + (size_t)(kt * 128 + lr) * HD + lc;
        const uint32_t kd = kdst0 + buf * 2 * PLN;
        #pragma unroll
        for (int i = 0; i < 4; i++) {
            cpa16(kd + i * 16, kp + i * 8);
            cpa16(kd + PLN + i * 16, vp + i * 8);
        }
        CP_COMMIT();
    };

    const uint32_t a_off = (uint32_t)(wm * 32 + (lane & 15)) * STR + ((lane >> 4) << 4);
    const uint32_t b_off = (uint32_t)(wn * 32 + (lane & 7) + ((lane >> 4) << 3)) * STR
                         + (((lane >> 3) & 1) << 4);
    const uint32_t vt_off = (uint32_t)(lane & 15) * STR
                          + (wn * 32 + ((lane >> 4) << 3)) * 2;
    const uint32_t qh_b = smem_u32(Qh) + a_off;
    const uint32_t ph_b = smem_u32(Pp) + a_off;

    float o[2][4][4];
    float m_[2][2], l_[2][2], corr[2][2];
    #pragma unroll
    for (int mi = 0; mi < 2; mi++)
        #pragma unroll
        for (int rr = 0; rr < 2; rr++) { m_[mi][rr] = -1e30f; l_[mi][rr] = 0.f; }
    #pragma unroll
    for (int mi = 0; mi < 2; mi++)
        #pragma unroll
        for (int nj = 0; nj < 4; nj++)
            #pragma unroll
            for (int r = 0; r < 4; r++) o[mi][nj][r] = 0.f;

    const int rbase = wm * 32 + (lane >> 2);
    const int cq = (lane & 3) * 2;

    issueKV(0, 0);

    for (int kt = 0; kt <= qt; kt++) {
        const int cur = kt & 1;
        CP_WAIT(0);
        __syncthreads();   // KV(kt) visible; all warps done with buffer cur^1

        const uint32_t kh_b = smem_u32(sm) + (2 + 2 * cur) * PLN + b_off;
        const uint32_t vt_b = smem_u32(sm) + (3 + 2 * cur) * PLN + vt_off;
        const int k0 = kt * 128;

        // ---- S = Q K^T ----
        float s[2][4][4];
        #pragma unroll
        for (int mi = 0; mi < 2; mi++)
            #pragma unroll
            for (int nj = 0; nj < 4; nj++)
                #pragma unroll
                for (int r = 0; r < 4; r++) s[mi][nj][r] = 0.f;
        #pragma unroll
        for (int kk = 0; kk < 8; kk++) {
            uint32_t aH[2][4], bF[2][4];
            ldsm4(aH[0], qh_b + kk * 32);
            ldsm4(aH[1], qh_b + kk * 32 + 16 * STR);
            #pragma unroll
            for (int j2 = 0; j2 < 2; j2++) ldsm4(bF[j2], kh_b + kk * 32 + j2 * 16 * STR);
            #pragma unroll
            for (int mi = 0; mi < 2; mi++)
                #pragma unroll
                for (int j2 = 0; j2 < 2; j2++) {
                    mma16816(s[mi][2*j2],   aH[mi], &bF[j2][0]);
                    mma16816(s[mi][2*j2+1], aH[mi], &bF[j2][2]);
                }
        }

        // prefetch next KV during ALU phase (buffer cur^1 is free: see barrier)
        if (kt < qt) issueKV(kt + 1, cur ^ 1);

        // ---- alibi + (diag-only) causal mask + partial row max ----
        const float colf = (float)(k0 + wn * 32 + cq);
        #pragma unroll
        for (int mi = 0; mi < 2; mi++) {
            #pragma unroll
            for (int rr = 0; rr < 2; rr++) {
                const int rloc = rbase + mi * 16 + rr * 8;
                float mx = -1e30f;
                if (kt == qt) {
                    const int rowg = q0 + rloc;
                    #pragma unroll
                    for (int nj = 0; nj < 4; nj++) {
                        #pragma unroll
                        for (int e = 0; e < 2; e++) {
                            float v = fmaf(slope, colf + (float)(nj * 8 + e), s[mi][nj][rr*2+e]);
                            if ((k0 + wn*32 + nj*8 + cq + e) > rowg) v = -1e30f;
                            s[mi][nj][rr*2+e] = v;
                            mx = fmaxf(mx, v);
                        }
                    }
                } else {
                    #pragma unroll
                    for (int nj = 0; nj < 4; nj++) {
                        #pragma unroll
                        for (int e = 0; e < 2; e++) {
                            float v = fmaf(slope, colf + (float)(nj * 8 + e), s[mi][nj][rr*2+e]);
                            s[mi][nj][rr*2+e] = v;
                            mx = fmaxf(mx, v);
                        }
                    }
                }
                mx = fmaxf(mx, __shfl_xor_sync(0xffffffffu, mx, 1));
                mx = fmaxf(mx, __shfl_xor_sync(0xffffffffu, mx, 2));
                if ((lane & 3) == 0) red_mx[wn][rloc] = mx;
            }
        }
        BARG(barid);

        // ---- softmax (group-local) ----
        #pragma unroll
        for (int mi = 0; mi < 2; mi++) {
            #pragma unroll
            for (int rr = 0; rr < 2; rr++) {
                const int rloc = rbase + mi * 16 + rr * 8;
                const float mx = fmaxf(fmaxf(red_mx[0][rloc], red_mx[1][rloc]),
                                       fmaxf(red_mx[2][rloc], red_mx[3][rloc]));
                const float mnew = fmaxf(m_[mi][rr], mx);
                const float cr = __expf(m_[mi][rr] - mnew);
                corr[mi][rr] = cr;
                m_[mi][rr] = mnew;
                float ls = 0.f;
                #pragma unroll
                for (int nj = 0; nj < 4; nj++) {
                    #pragma unroll
                    for (int e = 0; e < 2; e++) {
                        float p = __expf(s[mi][nj][rr*2+e] - mnew);
                        s[mi][nj][rr*2+e] = p;
                        ls += p;
                    }
                }
                ls += __shfl_xor_sync(0xffffffffu, ls, 1);
                ls += __shfl_xor_sync(0xffffffffu, ls, 2);
                if ((lane & 3) == 0) red_sm[wn][rloc] = ls;
                #pragma unroll
                for (int nj = 0; nj < 4; nj++) {
                    o[mi][nj][rr*2]   *= cr;
                    o[mi][nj][rr*2+1] *= cr;
                }
                const uint32_t roff = (uint32_t)rloc * STR + (wn * 32 + cq) * 2;
                #pragma unroll
                for (int nj = 0; nj < 4; nj++)
                    *(uint32_t*)(Pp + roff + nj * 16) =
                        pack_h(s[mi][nj][rr*2], s[mi][nj][rr*2+1]);
            }
        }
        BARG(barid);
        #pragma unroll
        for (int mi = 0; mi < 2; mi++)
            #pragma unroll
            for (int rr = 0; rr < 2; rr++) {
                const int rloc = rbase + mi * 16 + rr * 8;
                l_[mi][rr] = l_[mi][rr] * corr[mi][rr]
                           + red_sm[0][rloc] + red_sm[1][rloc]
                           + red_sm[2][rloc] + red_sm[3][rloc];
            }

        // ---- O += P V ----
        #pragma unroll
        for (int kk = 0; kk < 8; kk++) {
            uint32_t aP[2][4], bT[2][4];
            ldsm4(aP[0], ph_b + kk * 32);
            ldsm4(aP[1], ph_b + kk * 32 + 16 * STR);
            #pragma unroll
            for (int jp = 0; jp < 2; jp++)
                ldsm4t(bT[jp], vt_b + kk * 16 * STR + jp * 32);
            #pragma unroll
            for (int mi = 0; mi < 2; mi++)
                #pragma unroll
                for (int jp = 0; jp < 2; jp++) {
                    mma16816(o[mi][2*jp],   aP[mi], &bT[jp][0]);
                    mma16816(o[mi][2*jp+1], aP[mi], &bT[jp][2]);
                }
        }
        // no end-of-loop barrier: next iteration's top __syncthreads covers reuse
    }

    // ---- epilogue -> fp16 ctx ----
    const int b = bh >> 5, h = bh & 31;
    #pragma unroll
    for (int mi = 0; mi < 2; mi++) {
        #pragma unroll
        for (int rr = 0; rr < 2; rr++) {
            const float invl = 1.f / l_[mi][rr];
            const int srow = q0 + rbase + mi * 16 + rr * 8;
            __half* op = g_ctxh + ((size_t)(b * SEQ + srow)) * HID + h * HD
                       + wn * 32 + cq;
            #pragma unroll
            for (int nj = 0; nj < 4; nj++)
                *(uint32_t*)(op + nj * 8) = pack_h(o[mi][nj][rr*2] * invl,
                                                   o[mi][nj][rr*2+1] * invl);
        }
    }
}

// =============================== launch ====================================
extern "C" void kernel_launch(void* const* d_in, const int* in_sizes, int n_in,
                              void* d_out, int out_size)
{
    const float* hs    = (const float*)d_in[0];
    const float* resid = (const float*)d_in[1];
    const float* alibi = (const float*)d_in[2];
    const float* Wqkv  = (const float*)d_in[4];
    const float* bqkv  = (const float*)d_in[5];
    const float* Wd    = (const float*)d_in[6];
    const float* bd    = (const float*)d_in[7];
    float* out = (float*)d_out;

    cudaFuncSetAttribute(gemm_mma_kernel<true>,
                         cudaFuncAttributeMaxDynamicSharedMemorySize, GEMM_SMEM);
    cudaFuncSetAttribute(gemm_mma_kernel<false>,
                         cudaFuncAttributeMaxDynamicSharedMemorySize, GEMM_SMEM);
    cudaFuncSetAttribute(attn_mma_kernel,
                         cudaFuncAttributeMaxDynamicSharedMemorySize, ATT_SMEM);

    __half* d_ah;    cudaGetSymbolAddress((void**)&d_ah,    g_ah);
    __half* d_wqkvT; cudaGetSymbolAddress((void**)&d_wqkvT, g_wqkvT);
    __half* d_wdT;   cudaGetSymbolAddress((void**)&d_wdT,   g_wdT);
    __half* d_ctxh;  cudaGetSymbolAddress((void**)&d_ctxh,  g_ctxh);

    conv_fp16_kernel<<<(MROWS * HID / 4 + 255) / 256, 256>>>(hs, d_ah, MROWS * HID / 4);
    transpose_fp16_kernel<<<dim3(NQKV / 32, HID / 32), dim3(32, 8)>>>(Wqkv, d_wqkvT, HID, NQKV);
    transpose_fp16_kernel<<<dim3(HID / 32, HID / 32), dim3(32, 8)>>>(Wd, d_wdT, HID, HID);

    gemm_mma_kernel<true><<<dim3(NQKV/128, MROWS/256), 512, GEMM_SMEM>>>(d_ah, d_wqkvT, bqkv, nullptr, nullptr);
    attn_mma_kernel<<<dim3(SEQ/128, BATCH*NH), 512, ATT_SMEM>>>(alibi);
    gemm_mma_kernel<false><<<dim3(HID/128, MROWS/256), 512, GEMM_SMEM>>>(d_ctxh, d_wdT, bd, resid, out);
}